// round 12
// baseline (speedup 1.0000x reference)
#include <cuda_runtime.h>
#include <cuda_bf16.h>
#include <cuda_fp16.h>
#include <math.h>
#include <stdint.h>

// Problem dims
#define NN      8192
#define IN_DIM  1024
#define H1      512
#define H2      256
#define ZD      192
#define CAP     192

// ---------------- device scratch ----------------
__device__ float g_t1[NN * H1];
__device__ float g_t2[NN * H2];
__device__ float g_tm[NN * ZD];
__device__ __nv_bfloat16 g_xh [NN * IN_DIM];
__device__ __nv_bfloat16 g_xl [NN * IN_DIM];
__device__ __nv_bfloat16 g_x1h[NN * H1];
__device__ __nv_bfloat16 g_x1l[NN * H1];
__device__ __nv_bfloat16 g_x2h[NN * H2];
__device__ __nv_bfloat16 g_x2l[NN * H2];
__device__ __nv_bfloat16 g_zh [NN * ZD];
__device__ __nv_bfloat16 g_zl [NN * ZD];
__device__ __half        g_zf [NN * ZD];
__device__ __half        g_tzf[NN * ZD];
__device__ __nv_bfloat16 g_W1h[H1 * IN_DIM];
__device__ __nv_bfloat16 g_W1l[H1 * IN_DIM];
__device__ __nv_bfloat16 g_W2h[H2 * H1];
__device__ __nv_bfloat16 g_W2l[H2 * H1];
__device__ __nv_bfloat16 g_Wmh[ZD * H2];
__device__ __nv_bfloat16 g_Wml[ZD * H2];
__device__ __nv_bfloat16 g_Wth[ZD * ZD];
__device__ __nv_bfloat16 g_Wtl[ZD * ZD];
__device__ float g_vals[NN * CAP];
__device__ int   g_cols[NN * CAP];
__device__ int   g_cnt [NN];

// ---------------- helpers ----------------
__device__ __forceinline__ void split2(float v0, float v1, uint32_t& hi, uint32_t& lo) {
    __nv_bfloat16 h0 = __float2bfloat16_rn(v0);
    __nv_bfloat16 h1 = __float2bfloat16_rn(v1);
    __nv_bfloat16 l0 = __float2bfloat16_rn(v0 - __bfloat162float(h0));
    __nv_bfloat16 l1 = __float2bfloat16_rn(v1 - __bfloat162float(h1));
    hi = (uint32_t)__bfloat16_as_ushort(h0) | ((uint32_t)__bfloat16_as_ushort(h1) << 16);
    lo = (uint32_t)__bfloat16_as_ushort(l0) | ((uint32_t)__bfloat16_as_ushort(l1) << 16);
}

__device__ __forceinline__ uint32_t h2_as_u32(__half2 h) {
    uint32_t u;
    memcpy(&u, &h, 4);
    return u;
}

__device__ __forceinline__ void ldsm4(uint32_t& r0, uint32_t& r1, uint32_t& r2,
                                      uint32_t& r3, uint32_t addr) {
    asm volatile("ldmatrix.sync.aligned.m8n8.x4.shared.b16 {%0,%1,%2,%3}, [%4];"
                 : "=r"(r0), "=r"(r1), "=r"(r2), "=r"(r3) : "r"(addr));
}

__device__ __forceinline__ void mma_bf16(float (&d)[4], const uint32_t (&a)[4],
                                         uint32_t b0, uint32_t b1) {
    asm volatile(
        "mma.sync.aligned.m16n8k16.row.col.f32.bf16.bf16.f32 "
        "{%0,%1,%2,%3}, {%4,%5,%6,%7}, {%8,%9}, {%0,%1,%2,%3};"
        : "+f"(d[0]), "+f"(d[1]), "+f"(d[2]), "+f"(d[3])
        : "r"(a[0]), "r"(a[1]), "r"(a[2]), "r"(a[3]), "r"(b0), "r"(b1));
}

__device__ __forceinline__ void mma_f16(float (&d)[4], const uint32_t (&a)[4],
                                        uint32_t b0, uint32_t b1) {
    asm volatile(
        "mma.sync.aligned.m16n8k16.row.col.f32.f16.f16.f32 "
        "{%0,%1,%2,%3}, {%4,%5,%6,%7}, {%8,%9}, {%0,%1,%2,%3};"
        : "+f"(d[0]), "+f"(d[1]), "+f"(d[2]), "+f"(d[3])
        : "r"(a[0]), "r"(a[1]), "r"(a[2]), "r"(a[3]), "r"(b0), "r"(b1));
}

__device__ __forceinline__ void cp16(uint32_t dst, const void* src, bool v) {
    int sz = v ? 16 : 0;
    asm volatile("cp.async.cg.shared.global [%0], [%1], 16, %2;\n"
                 :: "r"(dst), "l"(src), "r"(sz) : "memory");
}
__device__ __forceinline__ void cp_commit() {
    asm volatile("cp.async.commit_group;" ::: "memory");
}
template <int n>
__device__ __forceinline__ void cp_wait() {
    asm volatile("cp.async.wait_group %0;" :: "n"(n) : "memory");
}

// ---------------- merged split: fp32 -> bf16 hi/lo planes, 7 segments ----------------
#define NSEG 7
struct SplitArgs {
    const float4* src[NSEG];
    uint32_t*     hi [NSEG];
    uint32_t*     lo [NSEG];
    int blk_off[NSEG + 1];
    int nq[NSEG];
};

__global__ void __launch_bounds__(256) split_all_kernel(SplitArgs a) {
    int b = blockIdx.x;
    int s = 0;
    #pragma unroll
    for (int k = 1; k < NSEG; k++)
        if (b >= a.blk_off[k]) s = k;
    int i = (b - a.blk_off[s]) * 256 + threadIdx.x;
    if (i >= a.nq[s]) return;
    float4 v = a.src[s][i];
    uint32_t h0, l0, h1, l1;
    split2(v.x, v.y, h0, l0);
    split2(v.z, v.w, h1, l1);
    a.hi[s][i * 2]     = h0; a.hi[s][i * 2 + 1] = h1;
    a.lo[s][i * 2]     = l0; a.lo[s][i * 2 + 1] = l1;
}

// ---------------- CSR build ----------------
__global__ void build_csr_kernel(const float* __restrict__ adj) {
    int row  = blockIdx.x * (blockDim.x >> 5) + (threadIdx.x >> 5);
    int lane = threadIdx.x & 31;
    if (row >= NN) return;
    const float* arow = adj + (size_t)row * NN;
    int cnt = 0;
    for (int c0 = 0; c0 < NN; c0 += 128) {
        float4 v = *(const float4*)(arow + c0 + lane * 4);
        unsigned m = (v.x != 0.f ? 1u : 0u) | (v.y != 0.f ? 2u : 0u)
                   | (v.z != 0.f ? 4u : 0u) | (v.w != 0.f ? 8u : 0u);
        int c = __popc(m);
        int s = c;
        #pragma unroll
        for (int d = 1; d < 32; d <<= 1) {
            int t = __shfl_up_sync(0xffffffffu, s, d);
            if (lane >= d) s += t;
        }
        int pos = cnt + s - c;
        int base = c0 + lane * 4;
        float vv[4] = {v.x, v.y, v.z, v.w};
        #pragma unroll
        for (int e = 0; e < 4; e++) {
            if ((m >> e) & 1u) {
                if (pos < CAP) {
                    g_cols[row * CAP + pos] = base + e;
                    g_vals[row * CAP + pos] = vv[e];
                }
                pos++;
            }
        }
        cnt += __shfl_sync(0xffffffffu, s, 31);
    }
    if (lane == 0) g_cnt[row] = (cnt < CAP) ? cnt : CAP;
}

// ---------------- SpMM, float4-vectorized, software-pipelined gathers ----------------
// Each thread owns 4 consecutive columns of one row. ncq = ncols/4.
// Prefetches the next nnz-group while accumulating the current one (same math order).
template <int MODE>
__global__ void __launch_bounds__(256) spmm4_kernel(
    const float4* __restrict__ X, int ncq, int rpc,
    float4* __restrict__ out_f32,
    uint2* __restrict__ hi, uint2* __restrict__ lo,
    uint2* __restrict__ f16out)
{
    int t = threadIdx.x;
    int r = t / ncq;
    int c = t - r * ncq;
    int row = blockIdx.x * rpc + r;
    if (r >= rpc || row >= NN) return;

    int cnt = g_cnt[row];
    const int*   cols = g_cols + row * CAP;
    const float* vals = g_vals + row * CAP;

    float4 a0 = {0,0,0,0}, a1 = {0,0,0,0}, a2 = {0,0,0,0}, a3 = {0,0,0,0};
    int j = 0;
    if (cnt >= 4) {
        // preload group 0
        int   c0 = cols[0], c1 = cols[1], c2 = cols[2], c3 = cols[3];
        float v0 = vals[0], v1 = vals[1], v2 = vals[2], v3 = vals[3];
        float4 x0 = X[(size_t)c0 * ncq + c];
        float4 x1 = X[(size_t)c1 * ncq + c];
        float4 x2 = X[(size_t)c2 * ncq + c];
        float4 x3 = X[(size_t)c3 * ncq + c];
        for (; j + 8 <= cnt; j += 4) {
            // prefetch group j+4 (independent of FMAs below)
            int   nc0 = cols[j+4], nc1 = cols[j+5], nc2 = cols[j+6], nc3 = cols[j+7];
            float nv0 = vals[j+4], nv1 = vals[j+5], nv2 = vals[j+6], nv3 = vals[j+7];
            float4 nx0 = X[(size_t)nc0 * ncq + c];
            float4 nx1 = X[(size_t)nc1 * ncq + c];
            float4 nx2 = X[(size_t)nc2 * ncq + c];
            float4 nx3 = X[(size_t)nc3 * ncq + c];
            // accumulate current group
            a0.x += v0 * x0.x; a0.y += v0 * x0.y; a0.z += v0 * x0.z; a0.w += v0 * x0.w;
            a1.x += v1 * x1.x; a1.y += v1 * x1.y; a1.z += v1 * x1.z; a1.w += v1 * x1.w;
            a2.x += v2 * x2.x; a2.y += v2 * x2.y; a2.z += v2 * x2.z; a2.w += v2 * x2.w;
            a3.x += v3 * x3.x; a3.y += v3 * x3.y; a3.z += v3 * x3.z; a3.w += v3 * x3.w;
            v0 = nv0; v1 = nv1; v2 = nv2; v3 = nv3;
            x0 = nx0; x1 = nx1; x2 = nx2; x3 = nx3;
        }
        // last full group
        a0.x += v0 * x0.x; a0.y += v0 * x0.y; a0.z += v0 * x0.z; a0.w += v0 * x0.w;
        a1.x += v1 * x1.x; a1.y += v1 * x1.y; a1.z += v1 * x1.z; a1.w += v1 * x1.w;
        a2.x += v2 * x2.x; a2.y += v2 * x2.y; a2.z += v2 * x2.z; a2.w += v2 * x2.w;
        a3.x += v3 * x3.x; a3.y += v3 * x3.y; a3.z += v3 * x3.z; a3.w += v3 * x3.w;
        j += 4;
    }
    for (; j < cnt; j++) {
        float v = vals[j];
        float4 xv = X[(size_t)cols[j] * ncq + c];
        a0.x += v * xv.x; a0.y += v * xv.y; a0.z += v * xv.z; a0.w += v * xv.w;
    }
    float4 acc;
    acc.x = (a0.x + a1.x) + (a2.x + a3.x);
    acc.y = (a0.y + a1.y) + (a2.y + a3.y);
    acc.z = (a0.z + a1.z) + (a2.z + a3.z);
    acc.w = (a0.w + a1.w) + (a2.w + a3.w);

    size_t o = (size_t)row * ncq + c;
    float4 rr;
    if (MODE == 1) {
        rr.x = acc.x > 0.f ? acc.x : 0.f;
        rr.y = acc.y > 0.f ? acc.y : 0.f;
        rr.z = acc.z > 0.f ? acc.z : 0.f;
        rr.w = acc.w > 0.f ? acc.w : 0.f;
    } else {
        rr = acc;
    }
    uint2 h, l;
    split2(rr.x, rr.y, h.x, l.x);
    split2(rr.z, rr.w, h.y, l.y);
    hi[o] = h;
    lo[o] = l;
    if (MODE == 0) {
        uint2 f;
        f.x = h2_as_u32(__floats2half2_rn(rr.x, rr.y));
        f.y = h2_as_u32(__floats2half2_rn(rr.z, rr.w));
        f16out[o] = f;
        out_f32[o] = acc;
    } else {
        float4 s;
        s.x = 1.0f / (1.0f + __expf(-rr.x));
        s.y = 1.0f / (1.0f + __expf(-rr.y));
        s.z = 1.0f / (1.0f + __expf(-rr.z));
        s.w = 1.0f / (1.0f + __expf(-rr.w));
        out_f32[o] = s;
    }
}

// ---------------- bf16x3 mma.sync GEMM, 128x64 tiles ----------------
#define GBM 128
#define GBN 64
#define GBK 32
#define STG_BYTES 24576
#define NSTAGE 3
#define SMEM_BYTES (NSTAGE * STG_BYTES)
#define PL_AH 0
#define PL_AL 8192
#define PL_BH 16384
#define PL_BL 20480

__device__ __forceinline__ uint32_t sw_off(int r, int kc) {
    return (uint32_t)(r * 64 + ((kc ^ ((r >> 1) & 3)) << 4));
}

// EPI 0: fp32 store. EPI 1: +bias, leaky_relu(0.1) -> fp16 plane only.
template <int EPI>
__global__ void __launch_bounds__(128, 3) gemm3(
    const __nv_bfloat16* __restrict__ Ah, const __nv_bfloat16* __restrict__ Al,
    const __nv_bfloat16* __restrict__ Bh, const __nv_bfloat16* __restrict__ Bl,
    const float* __restrict__ bias, float* __restrict__ C,
    __half* __restrict__ Cf,
    int M, int N, int K, int ldc)
{
    extern __shared__ uint8_t smem[];
    const uint32_t sbase = (uint32_t)__cvta_generic_to_shared(smem);

    const int tid  = threadIdx.x;
    const int lane = tid & 31;
    const int wid  = tid >> 5;
    const int wm   = wid & 1;
    const int wn   = wid >> 1;
    const int m0   = blockIdx.y * GBM;
    const int n0   = blockIdx.x * GBN;

    float acc[4][4][4];
    #pragma unroll
    for (int i = 0; i < 4; i++)
        #pragma unroll
        for (int j = 0; j < 4; j++)
            #pragma unroll
            for (int q = 0; q < 4; q++) acc[i][j][q] = 0.f;

    auto load_tile = [&](int it, int s) {
        int k0 = it * GBK;
        uint32_t st = sbase + s * STG_BYTES;
        #pragma unroll
        for (int i = 0; i < 4; i++) {
            int f = tid + i * 128;
            int r = f >> 2, c = f & 3;
            uint32_t doff = sw_off(r, c);
            size_t aoff = (size_t)(m0 + r) * K + k0 + c * 8;
            cp16(st + PL_AH + doff, Ah + aoff, true);
            cp16(st + PL_AL + doff, Al + aoff, true);
        }
        #pragma unroll
        for (int i = 0; i < 2; i++) {
            int f = tid + i * 128;
            int r = f >> 2, c = f & 3;
            uint32_t doff = sw_off(r, c);
            bool bv = (n0 + r) < N;
            int  br = bv ? (n0 + r) : 0;
            size_t boff = (size_t)br * K + k0 + c * 8;
            cp16(st + PL_BH + doff, Bh + boff, bv);
            cp16(st + PL_BL + doff, Bl + boff, bv);
        }
        cp_commit();
    };

    const int nIt = K / GBK;
    load_tile(0, 0);
    if (nIt > 1) load_tile(1, 1);

    for (int it = 0; it < nIt; it++) {
        if (it + 1 < nIt) cp_wait<1>(); else cp_wait<0>();
        __syncthreads();
        if (it + 2 < nIt) load_tile(it + 2, (it + 2) % NSTAGE);

        uint32_t st = sbase + (it % NSTAGE) * STG_BYTES;
        #pragma unroll
        for (int ks = 0; ks < 2; ks++) {
            uint32_t ah[4][4], al[4][4], bh[2][4], bl[2][4];
            #pragma unroll
            for (int g = 0; g < 2; g++) {
                int rr = wn * 32 + g * 16 + (lane >> 4) * 8 + (lane & 7);
                int kc = ks * 2 + ((lane >> 3) & 1);
                uint32_t off = sw_off(rr, kc);
                ldsm4(bh[g][0], bh[g][1], bh[g][2], bh[g][3], st + PL_BH + off);
                ldsm4(bl[g][0], bl[g][1], bl[g][2], bl[g][3], st + PL_BL + off);
            }
            #pragma unroll
            for (int mt = 0; mt < 4; mt++) {
                int rr = wm * 64 + mt * 16 + ((lane >> 3) & 1) * 8 + (lane & 7);
                int kc = ks * 2 + (lane >> 4);
                uint32_t off = sw_off(rr, kc);
                ldsm4(ah[mt][0], ah[mt][1], ah[mt][2], ah[mt][3], st + PL_AH + off);
                ldsm4(al[mt][0], al[mt][1], al[mt][2], al[mt][3], st + PL_AL + off);
            }
            #pragma unroll
            for (int mt = 0; mt < 4; mt++)
                #pragma unroll
                for (int nt = 0; nt < 4; nt++) {
                    uint32_t b0 = bh[nt >> 1][(nt & 1) * 2];
                    uint32_t b1 = bh[nt >> 1][(nt & 1) * 2 + 1];
                    mma_bf16(acc[mt][nt], ah[mt], b0, b1);
                    mma_bf16(acc[mt][nt], al[mt], b0, b1);
                    mma_bf16(acc[mt][nt], ah[mt],
                             bl[nt >> 1][(nt & 1) * 2], bl[nt >> 1][(nt & 1) * 2 + 1]);
                }
        }
        __syncthreads();
    }

    #pragma unroll
    for (int mt = 0; mt < 4; mt++) {
        int row = m0 + wm * 64 + mt * 16 + (lane >> 2);
        #pragma unroll
        for (int nt = 0; nt < 4; nt++) {
            int col = n0 + wn * 32 + nt * 8 + (lane & 3) * 2;
            if (col < N) {
                float c0 = acc[mt][nt][0], c1 = acc[mt][nt][1];
                float c2 = acc[mt][nt][2], c3 = acc[mt][nt][3];
                if (EPI == 1) {
                    float b0 = bias[col], b1 = bias[col + 1];
                    c0 += b0; c1 += b1; c2 += b0; c3 += b1;
                    c0 = (c0 >= 0.f) ? c0 : 0.1f * c0;
                    c1 = (c1 >= 0.f) ? c1 : 0.1f * c1;
                    c2 = (c2 >= 0.f) ? c2 : 0.1f * c2;
                    c3 = (c3 >= 0.f) ? c3 : 0.1f * c3;
                    *(__half2*)(Cf + (size_t)row * ldc + col)       = __floats2half2_rn(c0, c1);
                    *(__half2*)(Cf + (size_t)(row + 8) * ldc + col) = __floats2half2_rn(c2, c3);
                } else {
                    *(float2*)(C + (size_t)row * ldc + col)       = make_float2(c0, c1);
                    *(float2*)(C + (size_t)(row + 8) * ldc + col) = make_float2(c2, c3);
                }
            }
        }
    }
}

// ---------------- fp16 single-pass pred kernel ----------------
#define PF_SMEM 98304

__global__ void __launch_bounds__(128, 2) pred_f16(
    const __half* __restrict__ Af, const __half* __restrict__ Bf,
    float* __restrict__ C)
{
    extern __shared__ uint8_t smem[];
    const uint32_t sbase = (uint32_t)__cvta_generic_to_shared(smem);
    const int tid  = threadIdx.x;
    const int lane = tid & 31;
    const int wid  = tid >> 5;
    const int wm   = wid & 1;
    const int wn   = wid >> 1;
    const int m0   = blockIdx.y * 128;
    const int n0   = blockIdx.x * 128;

    #pragma unroll
    for (int i = 0; i < 24; i++) {
        int f = tid + i * 128;
        int r = f / 24, c = f % 24;
        int sub = c >> 3, cc = c & 7;
        uint32_t doff = (uint32_t)(sub * 16384 + r * 128 + ((cc ^ (r & 7)) << 4));
        cp16(sbase + doff,         Af + (size_t)(m0 + r) * ZD + c * 8, true);
        cp16(sbase + 49152 + doff, Bf + (size_t)(n0 + r) * ZD + c * 8, true);
    }
    cp_commit();
    cp_wait<0>();
    __syncthreads();

    float acc[4][8][4];
    #pragma unroll
    for (int i = 0; i < 4; i++)
        #pragma unroll
        for (int j = 0; j < 8; j++)
            #pragma unroll
            for (int q = 0; q < 4; q++) acc[i][j][q] = 0.f;

    #pragma unroll
    for (int ks = 0; ks < 12; ks++) {
        int sub = ks >> 2;
        uint32_t sA = sbase + sub * 16384;
        uint32_t sB = sbase + 49152 + sub * 16384;
        uint32_t a[4][4], b[4][4];
        #pragma unroll
        for (int mt = 0; mt < 4; mt++) {
            int rr = wm * 64 + mt * 16 + ((lane >> 3) & 1) * 8 + (lane & 7);
            int kc = (ks & 3) * 2 + (lane >> 4);
            uint32_t off = (uint32_t)(rr * 128 + ((kc ^ (rr & 7)) << 4));
            ldsm4(a[mt][0], a[mt][1], a[mt][2], a[mt][3], sA + off);
        }
        #pragma unroll
        for (int g = 0; g < 4; g++) {
            int rr = wn * 64 + g * 16 + (lane >> 4) * 8 + (lane & 7);
            int kc = (ks & 3) * 2 + ((lane >> 3) & 1);
            uint32_t off = (uint32_t)(rr * 128 + ((kc ^ (rr & 7)) << 4));
            ldsm4(b[g][0], b[g][1], b[g][2], b[g][3], sB + off);
        }
        #pragma unroll
        for (int mt = 0; mt < 4; mt++)
            #pragma unroll
            for (int nt = 0; nt < 8; nt++)
                mma_f16(acc[mt][nt], a[mt],
                        b[nt >> 1][(nt & 1) * 2], b[nt >> 1][(nt & 1) * 2 + 1]);
    }

    #pragma unroll
    for (int mt = 0; mt < 4; mt++) {
        int row = m0 + wm * 64 + mt * 16 + (lane >> 2);
        #pragma unroll
        for (int nt = 0; nt < 8; nt++) {
            int col = n0 + wn * 64 + nt * 8 + (lane & 3) * 2;
            *(float2*)(C + (size_t)row * NN + col) =
                make_float2(acc[mt][nt][0], acc[mt][nt][1]);
            *(float2*)(C + (size_t)(row + 8) * NN + col) =
                make_float2(acc[mt][nt][2], acc[mt][nt][3]);
        }
    }
}

// ---------------- launch ----------------
static inline void* sym_addr(const void* sym) {
    void* p = nullptr;
    cudaGetSymbolAddress(&p, sym);
    return p;
}

extern "C" void kernel_launch(void* const* d_in, const int* in_sizes, int n_in,
                              void* d_out, int out_size)
{
    const float* adj = (const float*)d_in[0];
    const float* x   = (const float*)d_in[1];
    const float* W1  = (const float*)d_in[2];
    const float* W2  = (const float*)d_in[3];
    const float* Wm1 = (const float*)d_in[4];
    const float* Wm2 = (const float*)d_in[5];
    const float* Wm3 = (const float*)d_in[6];
    const float* Wt  = (const float*)d_in[7];
    const float* bt  = (const float*)d_in[8];

    float* out = (float*)d_out;
    float* out_pred = out;
    float* out_x1   = out + (size_t)NN * NN;
    float* out_x2   = out_x1 + (size_t)NN * H1;
    float* out_z    = out_x2 + (size_t)NN * H2;

    float* t1 = (float*)sym_addr(g_t1);
    float* t2 = (float*)sym_addr(g_t2);
    float* tm = (float*)sym_addr(g_tm);
    __nv_bfloat16* xh  = (__nv_bfloat16*)sym_addr(g_xh);
    __nv_bfloat16* xl  = (__nv_bfloat16*)sym_addr(g_xl);
    __nv_bfloat16* x1h = (__nv_bfloat16*)sym_addr(g_x1h);
    __nv_bfloat16* x1l = (__nv_bfloat16*)sym_addr(g_x1l);
    __nv_bfloat16* x2h = (__nv_bfloat16*)sym_addr(g_x2h);
    __nv_bfloat16* x2l = (__nv_bfloat16*)sym_addr(g_x2l);
    __nv_bfloat16* zh  = (__nv_bfloat16*)sym_addr(g_zh);
    __nv_bfloat16* zl  = (__nv_bfloat16*)sym_addr(g_zl);
    __half* zf  = (__half*)sym_addr(g_zf);
    __half* tzf = (__half*)sym_addr(g_tzf);
    __nv_bfloat16* W1h = (__nv_bfloat16*)sym_addr(g_W1h);
    __nv_bfloat16* W1l = (__nv_bfloat16*)sym_addr(g_W1l);
    __nv_bfloat16* W2h = (__nv_bfloat16*)sym_addr(g_W2h);
    __nv_bfloat16* W2l = (__nv_bfloat16*)sym_addr(g_W2l);
    __nv_bfloat16* Wmh = (__nv_bfloat16*)sym_addr(g_Wmh);
    __nv_bfloat16* Wml = (__nv_bfloat16*)sym_addr(g_Wml);
    __nv_bfloat16* Wth = (__nv_bfloat16*)sym_addr(g_Wth);
    __nv_bfloat16* Wtl = (__nv_bfloat16*)sym_addr(g_Wtl);

    cudaFuncSetAttribute((const void*)gemm3<0>,
                         cudaFuncAttributeMaxDynamicSharedMemorySize, SMEM_BYTES);
    cudaFuncSetAttribute((const void*)gemm3<1>,
                         cudaFuncAttributeMaxDynamicSharedMemorySize, SMEM_BYTES);
    cudaFuncSetAttribute((const void*)pred_f16,
                         cudaFuncAttributeMaxDynamicSharedMemorySize, PF_SMEM);

    // fork: CSR build (DRAM-bound) runs concurrently with split+t1 (tensor-bound)
    cudaStream_t s2;
    cudaEvent_t e_fork, e_join;
    cudaStreamCreateWithFlags(&s2, cudaStreamNonBlocking);
    cudaEventCreateWithFlags(&e_fork, cudaEventDisableTiming);
    cudaEventCreateWithFlags(&e_join, cudaEventDisableTiming);

    cudaEventRecord(e_fork, 0);
    cudaStreamWaitEvent(s2, e_fork, 0);
    build_csr_kernel<<<NN / 8, 256, 0, s2>>>(adj);
    cudaEventRecord(e_join, s2);

    // 0. merged split of all static inputs (single launch, default stream)
    {
        SplitArgs a;
        const float* srcs[NSEG] = {x, W1, W2, Wm1, Wm2, Wm3, Wt};
        __nv_bfloat16* his[NSEG] = {xh, W1h, W2h, Wmh, Wmh + 64 * H2, Wmh + 128 * H2, Wth};
        __nv_bfloat16* los[NSEG] = {xl, W1l, W2l, Wml, Wml + 64 * H2, Wml + 128 * H2, Wtl};
        int ns[NSEG] = {NN * IN_DIM / 4, H1 * IN_DIM / 4, H2 * H1 / 4,
                        64 * H2 / 4, 64 * H2 / 4, 64 * H2 / 4, ZD * ZD / 4};
        int off = 0;
        for (int s = 0; s < NSEG; s++) {
            a.src[s] = (const float4*)srcs[s];
            a.hi[s]  = (uint32_t*)his[s];
            a.lo[s]  = (uint32_t*)los[s];
            a.nq[s]  = ns[s];
            a.blk_off[s] = off;
            off += (ns[s] + 255) / 256;
        }
        a.blk_off[NSEG] = off;
        split_all_kernel<<<off, 256>>>(a);
    }

    // t1 = x @ W1^T  (overlaps with CSR build)
    gemm3<0><<<dim3(H1 / GBN, NN / GBM), 128, SMEM_BYTES>>>(
        xh, xl, W1h, W1l, nullptr, t1, nullptr, NN, H1, IN_DIM, H1);

    // join: spmm needs the CSR
    cudaStreamWaitEvent(0, e_join, 0);

    // x1 = relu(adj@t1) -> planes; out_x1 = sigmoid   (ncq=128, rpc=2, 256 thr)
    spmm4_kernel<1><<<NN / 2, 256>>>(
        (const float4*)t1, H1 / 4, 2, (float4*)out_x1,
        (uint2*)x1h, (uint2*)x1l, nullptr);
    // t2 = x1 @ W2^T
    gemm3<0><<<dim3(H2 / GBN, NN / GBM), 128, SMEM_BYTES>>>(
        x1h, x1l, W2h, W2l, nullptr, t2, nullptr, NN, H2, H1, H2);
    // x2 planes + sigmoid   (ncq=64, rpc=4)
    spmm4_kernel<1><<<NN / 4, 256>>>(
        (const float4*)t2, H2 / 4, 4, (float4*)out_x2,
        (uint2*)x2h, (uint2*)x2l, nullptr);
    // tm = x2 @ Wm^T
    gemm3<0><<<dim3(ZD / GBN, NN / GBM), 128, SMEM_BYTES>>>(
        x2h, x2l, Wmh, Wml, nullptr, tm, nullptr, NN, ZD, H2, ZD);
    // z = adj @ tm -> fp32 out + bf16 planes + fp16 plane  (ncq=48, rpc=5)
    spmm4_kernel<0><<<(NN + 4) / 5, 256>>>(
        (const float4*)tm, ZD / 4, 5, (float4*)out_z,
        (uint2*)zh, (uint2*)zl, (uint2*)zf);
    // tz = leaky(z @ Wt^T + bt) -> fp16 plane only
    gemm3<1><<<dim3(ZD / GBN, NN / GBM), 128, SMEM_BYTES>>>(
        zh, zl, Wth, Wtl, bt, nullptr, tzf, NN, ZD, ZD, ZD);
    // pred = zf @ tzf^T  (fp16 single pass)
    pred_f16<<<dim3(NN / 128, NN / 128), 128, PF_SMEM>>>(zf, tzf, out_pred);

    (void)in_sizes; (void)n_in; (void)out_size;
}

// round 13
// speedup vs baseline: 1.0607x; 1.0607x over previous
#include <cuda_runtime.h>
#include <cuda_bf16.h>
#include <cuda_fp16.h>
#include <math.h>
#include <stdint.h>

// Problem dims
#define NN      8192
#define IN_DIM  1024
#define H1      512
#define H2      256
#define ZD      192
#define CAP     192

// ---------------- device scratch ----------------
__device__ float g_t1[NN * H1];
__device__ float g_t2[NN * H2];
__device__ float g_tm[NN * ZD];
__device__ __nv_bfloat16 g_xh [NN * IN_DIM];
__device__ __nv_bfloat16 g_xl [NN * IN_DIM];
__device__ __nv_bfloat16 g_x1h[NN * H1];
__device__ __nv_bfloat16 g_x1l[NN * H1];
__device__ __nv_bfloat16 g_x2h[NN * H2];
__device__ __nv_bfloat16 g_x2l[NN * H2];
__device__ __nv_bfloat16 g_zh [NN * ZD];
__device__ __nv_bfloat16 g_zl [NN * ZD];
__device__ __half        g_zf [NN * ZD];
__device__ __half        g_tzf[NN * ZD];
__device__ __nv_bfloat16 g_W1h[H1 * IN_DIM];
__device__ __nv_bfloat16 g_W1l[H1 * IN_DIM];
__device__ __nv_bfloat16 g_W2h[H2 * H1];
__device__ __nv_bfloat16 g_W2l[H2 * H1];
__device__ __nv_bfloat16 g_Wmh[ZD * H2];
__device__ __nv_bfloat16 g_Wml[ZD * H2];
__device__ __nv_bfloat16 g_Wth[ZD * ZD];
__device__ __nv_bfloat16 g_Wtl[ZD * ZD];
__device__ float g_vals[NN * CAP];
__device__ int   g_cols[NN * CAP];
__device__ int   g_cnt [NN];

// ---------------- helpers ----------------
__device__ __forceinline__ void split2(float v0, float v1, uint32_t& hi, uint32_t& lo) {
    __nv_bfloat16 h0 = __float2bfloat16_rn(v0);
    __nv_bfloat16 h1 = __float2bfloat16_rn(v1);
    __nv_bfloat16 l0 = __float2bfloat16_rn(v0 - __bfloat162float(h0));
    __nv_bfloat16 l1 = __float2bfloat16_rn(v1 - __bfloat162float(h1));
    hi = (uint32_t)__bfloat16_as_ushort(h0) | ((uint32_t)__bfloat16_as_ushort(h1) << 16);
    lo = (uint32_t)__bfloat16_as_ushort(l0) | ((uint32_t)__bfloat16_as_ushort(l1) << 16);
}

__device__ __forceinline__ uint32_t h2_as_u32(__half2 h) {
    uint32_t u;
    memcpy(&u, &h, 4);
    return u;
}

__device__ __forceinline__ void ldsm4(uint32_t& r0, uint32_t& r1, uint32_t& r2,
                                      uint32_t& r3, uint32_t addr) {
    asm volatile("ldmatrix.sync.aligned.m8n8.x4.shared.b16 {%0,%1,%2,%3}, [%4];"
                 : "=r"(r0), "=r"(r1), "=r"(r2), "=r"(r3) : "r"(addr));
}

__device__ __forceinline__ void mma_bf16(float (&d)[4], const uint32_t (&a)[4],
                                         uint32_t b0, uint32_t b1) {
    asm volatile(
        "mma.sync.aligned.m16n8k16.row.col.f32.bf16.bf16.f32 "
        "{%0,%1,%2,%3}, {%4,%5,%6,%7}, {%8,%9}, {%0,%1,%2,%3};"
        : "+f"(d[0]), "+f"(d[1]), "+f"(d[2]), "+f"(d[3])
        : "r"(a[0]), "r"(a[1]), "r"(a[2]), "r"(a[3]), "r"(b0), "r"(b1));
}

__device__ __forceinline__ void mma_f16(float (&d)[4], const uint32_t (&a)[4],
                                        uint32_t b0, uint32_t b1) {
    asm volatile(
        "mma.sync.aligned.m16n8k16.row.col.f32.f16.f16.f32 "
        "{%0,%1,%2,%3}, {%4,%5,%6,%7}, {%8,%9}, {%0,%1,%2,%3};"
        : "+f"(d[0]), "+f"(d[1]), "+f"(d[2]), "+f"(d[3])
        : "r"(a[0]), "r"(a[1]), "r"(a[2]), "r"(a[3]), "r"(b0), "r"(b1));
}

__device__ __forceinline__ void cp16(uint32_t dst, const void* src, bool v) {
    int sz = v ? 16 : 0;
    asm volatile("cp.async.cg.shared.global [%0], [%1], 16, %2;\n"
                 :: "r"(dst), "l"(src), "r"(sz) : "memory");
}
__device__ __forceinline__ void cp_commit() {
    asm volatile("cp.async.commit_group;" ::: "memory");
}
template <int n>
__device__ __forceinline__ void cp_wait() {
    asm volatile("cp.async.wait_group %0;" :: "n"(n) : "memory");
}

// ---------------- merged split: fp32 -> bf16 hi/lo planes, 7 segments ----------------
#define NSEG 7
struct SplitArgs {
    const float4* src[NSEG];
    uint32_t*     hi [NSEG];
    uint32_t*     lo [NSEG];
    int blk_off[NSEG + 1];
    int nq[NSEG];
};

__global__ void __launch_bounds__(256) split_all_kernel(SplitArgs a) {
    int b = blockIdx.x;
    int s = 0;
    #pragma unroll
    for (int k = 1; k < NSEG; k++)
        if (b >= a.blk_off[k]) s = k;
    int i = (b - a.blk_off[s]) * 256 + threadIdx.x;
    if (i >= a.nq[s]) return;
    float4 v = a.src[s][i];
    uint32_t h0, l0, h1, l1;
    split2(v.x, v.y, h0, l0);
    split2(v.z, v.w, h1, l1);
    a.hi[s][i * 2]     = h0; a.hi[s][i * 2 + 1] = h1;
    a.lo[s][i * 2]     = l0; a.lo[s][i * 2 + 1] = l1;
}

// ---------------- SpMM, float4-vectorized (round-10 proven version) ----------------
template <int MODE>
__global__ void spmm4_kernel(
    const float4* __restrict__ X, int ncq, int rpc,
    float4* __restrict__ out_f32,
    uint2* __restrict__ hi, uint2* __restrict__ lo,
    uint2* __restrict__ f16out)
{
    int t = threadIdx.x;
    int r = t / ncq;
    int c = t - r * ncq;
    int row = blockIdx.x * rpc + r;
    if (r >= rpc || row >= NN) return;

    int cnt = g_cnt[row];
    const int*   cols = g_cols + row * CAP;
    const float* vals = g_vals + row * CAP;

    float4 a0 = {0,0,0,0}, a1 = {0,0,0,0}, a2 = {0,0,0,0}, a3 = {0,0,0,0};
    int j = 0;
    for (; j + 4 <= cnt; j += 4) {
        int   c0 = cols[j+0], c1 = cols[j+1], c2 = cols[j+2], c3 = cols[j+3];
        float v0 = vals[j+0], v1 = vals[j+1], v2 = vals[j+2], v3 = vals[j+3];
        float4 x0 = X[(size_t)c0 * ncq + c];
        float4 x1 = X[(size_t)c1 * ncq + c];
        float4 x2 = X[(size_t)c2 * ncq + c];
        float4 x3 = X[(size_t)c3 * ncq + c];
        a0.x += v0 * x0.x; a0.y += v0 * x0.y; a0.z += v0 * x0.z; a0.w += v0 * x0.w;
        a1.x += v1 * x1.x; a1.y += v1 * x1.y; a1.z += v1 * x1.z; a1.w += v1 * x1.w;
        a2.x += v2 * x2.x; a2.y += v2 * x2.y; a2.z += v2 * x2.z; a2.w += v2 * x2.w;
        a3.x += v3 * x3.x; a3.y += v3 * x3.y; a3.z += v3 * x3.z; a3.w += v3 * x3.w;
    }
    for (; j < cnt; j++) {
        float v = vals[j];
        float4 xv = X[(size_t)cols[j] * ncq + c];
        a0.x += v * xv.x; a0.y += v * xv.y; a0.z += v * xv.z; a0.w += v * xv.w;
    }
    float4 acc;
    acc.x = (a0.x + a1.x) + (a2.x + a3.x);
    acc.y = (a0.y + a1.y) + (a2.y + a3.y);
    acc.z = (a0.z + a1.z) + (a2.z + a3.z);
    acc.w = (a0.w + a1.w) + (a2.w + a3.w);

    size_t o = (size_t)row * ncq + c;
    float4 rr;
    if (MODE == 1) {
        rr.x = acc.x > 0.f ? acc.x : 0.f;
        rr.y = acc.y > 0.f ? acc.y : 0.f;
        rr.z = acc.z > 0.f ? acc.z : 0.f;
        rr.w = acc.w > 0.f ? acc.w : 0.f;
    } else {
        rr = acc;
    }
    uint2 h, l;
    split2(rr.x, rr.y, h.x, l.x);
    split2(rr.z, rr.w, h.y, l.y);
    hi[o] = h;
    lo[o] = l;
    if (MODE == 0) {
        uint2 f;
        f.x = h2_as_u32(__floats2half2_rn(rr.x, rr.y));
        f.y = h2_as_u32(__floats2half2_rn(rr.z, rr.w));
        f16out[o] = f;
        out_f32[o] = acc;
    } else {
        float4 s;
        s.x = 1.0f / (1.0f + __expf(-rr.x));
        s.y = 1.0f / (1.0f + __expf(-rr.y));
        s.z = 1.0f / (1.0f + __expf(-rr.z));
        s.w = 1.0f / (1.0f + __expf(-rr.w));
        out_f32[o] = s;
    }
}

// ---------------- bf16x3 mma.sync GEMM core (device body) ----------------
#define GBM 128
#define GBN 64
#define GBK 32
#define STG_BYTES 24576
#define NSTAGE 3
#define SMEM_BYTES (NSTAGE * STG_BYTES)
#define PL_AH 0
#define PL_AL 8192
#define PL_BH 16384
#define PL_BL 20480

__device__ __forceinline__ uint32_t sw_off(int r, int kc) {
    return (uint32_t)(r * 64 + ((kc ^ ((r >> 1) & 3)) << 4));
}

// EPI 0: fp32 store. EPI 1: +bias, leaky_relu(0.1) -> fp16 plane only.
template <int EPI>
__device__ __forceinline__ void gemm3_body(
    uint8_t* smem, int m0, int n0,
    const __nv_bfloat16* __restrict__ Ah, const __nv_bfloat16* __restrict__ Al,
    const __nv_bfloat16* __restrict__ Bh, const __nv_bfloat16* __restrict__ Bl,
    const float* __restrict__ bias, float* __restrict__ C,
    __half* __restrict__ Cf,
    int M, int N, int K, int ldc)
{
    const uint32_t sbase = (uint32_t)__cvta_generic_to_shared(smem);
    const int tid  = threadIdx.x;
    const int lane = tid & 31;
    const int wid  = tid >> 5;
    const int wm   = wid & 1;
    const int wn   = wid >> 1;

    float acc[4][4][4];
    #pragma unroll
    for (int i = 0; i < 4; i++)
        #pragma unroll
        for (int j = 0; j < 4; j++)
            #pragma unroll
            for (int q = 0; q < 4; q++) acc[i][j][q] = 0.f;

    auto load_tile = [&](int it, int s) {
        int k0 = it * GBK;
        uint32_t st = sbase + s * STG_BYTES;
        #pragma unroll
        for (int i = 0; i < 4; i++) {
            int f = tid + i * 128;
            int r = f >> 2, c = f & 3;
            uint32_t doff = sw_off(r, c);
            size_t aoff = (size_t)(m0 + r) * K + k0 + c * 8;
            cp16(st + PL_AH + doff, Ah + aoff, true);
            cp16(st + PL_AL + doff, Al + aoff, true);
        }
        #pragma unroll
        for (int i = 0; i < 2; i++) {
            int f = tid + i * 128;
            int r = f >> 2, c = f & 3;
            uint32_t doff = sw_off(r, c);
            bool bv = (n0 + r) < N;
            int  br = bv ? (n0 + r) : 0;
            size_t boff = (size_t)br * K + k0 + c * 8;
            cp16(st + PL_BH + doff, Bh + boff, bv);
            cp16(st + PL_BL + doff, Bl + boff, bv);
        }
        cp_commit();
    };

    const int nIt = K / GBK;
    load_tile(0, 0);
    if (nIt > 1) load_tile(1, 1);

    for (int it = 0; it < nIt; it++) {
        if (it + 1 < nIt) cp_wait<1>(); else cp_wait<0>();
        __syncthreads();
        if (it + 2 < nIt) load_tile(it + 2, (it + 2) % NSTAGE);

        uint32_t st = sbase + (it % NSTAGE) * STG_BYTES;
        #pragma unroll
        for (int ks = 0; ks < 2; ks++) {
            uint32_t ah[4][4], al[4][4], bh[2][4], bl[2][4];
            #pragma unroll
            for (int g = 0; g < 2; g++) {
                int rr = wn * 32 + g * 16 + (lane >> 4) * 8 + (lane & 7);
                int kc = ks * 2 + ((lane >> 3) & 1);
                uint32_t off = sw_off(rr, kc);
                ldsm4(bh[g][0], bh[g][1], bh[g][2], bh[g][3], st + PL_BH + off);
                ldsm4(bl[g][0], bl[g][1], bl[g][2], bl[g][3], st + PL_BL + off);
            }
            #pragma unroll
            for (int mt = 0; mt < 4; mt++) {
                int rr = wm * 64 + mt * 16 + ((lane >> 3) & 1) * 8 + (lane & 7);
                int kc = ks * 2 + (lane >> 4);
                uint32_t off = sw_off(rr, kc);
                ldsm4(ah[mt][0], ah[mt][1], ah[mt][2], ah[mt][3], st + PL_AH + off);
                ldsm4(al[mt][0], al[mt][1], al[mt][2], al[mt][3], st + PL_AL + off);
            }
            #pragma unroll
            for (int mt = 0; mt < 4; mt++)
                #pragma unroll
                for (int nt = 0; nt < 4; nt++) {
                    uint32_t b0 = bh[nt >> 1][(nt & 1) * 2];
                    uint32_t b1 = bh[nt >> 1][(nt & 1) * 2 + 1];
                    mma_bf16(acc[mt][nt], ah[mt], b0, b1);
                    mma_bf16(acc[mt][nt], al[mt], b0, b1);
                    mma_bf16(acc[mt][nt], ah[mt],
                             bl[nt >> 1][(nt & 1) * 2], bl[nt >> 1][(nt & 1) * 2 + 1]);
                }
        }
        __syncthreads();
    }

    #pragma unroll
    for (int mt = 0; mt < 4; mt++) {
        int row = m0 + wm * 64 + mt * 16 + (lane >> 2);
        #pragma unroll
        for (int nt = 0; nt < 4; nt++) {
            int col = n0 + wn * 32 + nt * 8 + (lane & 3) * 2;
            if (col < N) {
                float c0 = acc[mt][nt][0], c1 = acc[mt][nt][1];
                float c2 = acc[mt][nt][2], c3 = acc[mt][nt][3];
                if (EPI == 1) {
                    float b0 = bias[col], b1 = bias[col + 1];
                    c0 += b0; c1 += b1; c2 += b0; c3 += b1;
                    c0 = (c0 >= 0.f) ? c0 : 0.1f * c0;
                    c1 = (c1 >= 0.f) ? c1 : 0.1f * c1;
                    c2 = (c2 >= 0.f) ? c2 : 0.1f * c2;
                    c3 = (c3 >= 0.f) ? c3 : 0.1f * c3;
                    *(__half2*)(Cf + (size_t)row * ldc + col)       = __floats2half2_rn(c0, c1);
                    *(__half2*)(Cf + (size_t)(row + 8) * ldc + col) = __floats2half2_rn(c2, c3);
                } else {
                    *(float2*)(C + (size_t)row * ldc + col)       = make_float2(c0, c1);
                    *(float2*)(C + (size_t)(row + 8) * ldc + col) = make_float2(c2, c3);
                }
            }
        }
    }
}

template <int EPI>
__global__ void __launch_bounds__(128, 3) gemm3(
    const __nv_bfloat16* __restrict__ Ah, const __nv_bfloat16* __restrict__ Al,
    const __nv_bfloat16* __restrict__ Bh, const __nv_bfloat16* __restrict__ Bl,
    const float* __restrict__ bias, float* __restrict__ C,
    __half* __restrict__ Cf,
    int M, int N, int K, int ldc)
{
    extern __shared__ uint8_t smem[];
    gemm3_body<EPI>(smem, blockIdx.y * GBM, blockIdx.x * GBN,
                    Ah, Al, Bh, Bl, bias, C, Cf, M, N, K, ldc);
}

// ---------------- CSR row scan (device body, 4 warps/block, 1 row/warp) -------
__device__ __forceinline__ void csr_row_body(const float* __restrict__ adj, int row) {
    int lane = threadIdx.x & 31;
    const float* arow = adj + (size_t)row * NN;
    int cnt = 0;
    for (int c0 = 0; c0 < NN; c0 += 128) {
        float4 v = *(const float4*)(arow + c0 + lane * 4);
        unsigned m = (v.x != 0.f ? 1u : 0u) | (v.y != 0.f ? 2u : 0u)
                   | (v.z != 0.f ? 4u : 0u) | (v.w != 0.f ? 8u : 0u);
        int c = __popc(m);
        int s = c;
        #pragma unroll
        for (int d = 1; d < 32; d <<= 1) {
            int t = __shfl_up_sync(0xffffffffu, s, d);
            if (lane >= d) s += t;
        }
        int pos = cnt + s - c;
        int base = c0 + lane * 4;
        float vv[4] = {v.x, v.y, v.z, v.w};
        #pragma unroll
        for (int e = 0; e < 4; e++) {
            if ((m >> e) & 1u) {
                if (pos < CAP) {
                    g_cols[row * CAP + pos] = base + e;
                    g_vals[row * CAP + pos] = vv[e];
                }
                pos++;
            }
        }
        cnt += __shfl_sync(0xffffffffu, s, 31);
    }
    if (lane == 0) g_cnt[row] = (cnt < CAP) ? cnt : CAP;
}

// ---------------- fused t1 GEMM + CSR build ----------------
// 2560 blocks of 128 threads: bid%5==4 -> t1 gemm tile (512 tiles: 64 M x 8 N),
// else -> CSR scan of 4 rows (2048 blocks x 4 warps). Interleaving keeps a
// DRAM-bound : tensor-bound resident mix on every SM.
#define FUSE_BLOCKS 2560

__global__ void __launch_bounds__(128, 3) t1_csr_kernel(
    const float* __restrict__ adj,
    const __nv_bfloat16* __restrict__ Ah, const __nv_bfloat16* __restrict__ Al,
    const __nv_bfloat16* __restrict__ Bh, const __nv_bfloat16* __restrict__ Bl,
    float* __restrict__ C)
{
    extern __shared__ uint8_t smem[];
    int bid = blockIdx.x;
    if ((bid % 5) == 4) {
        int g = bid / 5;                      // 0..511
        int m0 = (g >> 3) * GBM;              // 64 M tiles
        int n0 = (g & 7) * GBN;               // 8 N tiles
        gemm3_body<0>(smem, m0, n0, Ah, Al, Bh, Bl,
                      nullptr, C, nullptr, NN, H1, IN_DIM, H1);
    } else {
        int cb = (bid / 5) * 4 + (bid % 5);   // 0..2047
        int row = cb * 4 + (threadIdx.x >> 5);
        if (row < NN) csr_row_body(adj, row);
    }
}

// ---------------- fp16 single-pass pred kernel ----------------
#define PF_SMEM 98304

__global__ void __launch_bounds__(128, 2) pred_f16(
    const __half* __restrict__ Af, const __half* __restrict__ Bf,
    float* __restrict__ C)
{
    extern __shared__ uint8_t smem[];
    const uint32_t sbase = (uint32_t)__cvta_generic_to_shared(smem);
    const int tid  = threadIdx.x;
    const int lane = tid & 31;
    const int wid  = tid >> 5;
    const int wm   = wid & 1;
    const int wn   = wid >> 1;
    const int m0   = blockIdx.y * 128;
    const int n0   = blockIdx.x * 128;

    #pragma unroll
    for (int i = 0; i < 24; i++) {
        int f = tid + i * 128;
        int r = f / 24, c = f % 24;
        int sub = c >> 3, cc = c & 7;
        uint32_t doff = (uint32_t)(sub * 16384 + r * 128 + ((cc ^ (r & 7)) << 4));
        cp16(sbase + doff,         Af + (size_t)(m0 + r) * ZD + c * 8, true);
        cp16(sbase + 49152 + doff, Bf + (size_t)(n0 + r) * ZD + c * 8, true);
    }
    cp_commit();
    cp_wait<0>();
    __syncthreads();

    float acc[4][8][4];
    #pragma unroll
    for (int i = 0; i < 4; i++)
        #pragma unroll
        for (int j = 0; j < 8; j++)
            #pragma unroll
            for (int q = 0; q < 4; q++) acc[i][j][q] = 0.f;

    #pragma unroll
    for (int ks = 0; ks < 12; ks++) {
        int sub = ks >> 2;
        uint32_t sA = sbase + sub * 16384;
        uint32_t sB = sbase + 49152 + sub * 16384;
        uint32_t a[4][4], b[4][4];
        #pragma unroll
        for (int mt = 0; mt < 4; mt++) {
            int rr = wm * 64 + mt * 16 + ((lane >> 3) & 1) * 8 + (lane & 7);
            int kc = (ks & 3) * 2 + (lane >> 4);
            uint32_t off = (uint32_t)(rr * 128 + ((kc ^ (rr & 7)) << 4));
            ldsm4(a[mt][0], a[mt][1], a[mt][2], a[mt][3], sA + off);
        }
        #pragma unroll
        for (int g = 0; g < 4; g++) {
            int rr = wn * 64 + g * 16 + (lane >> 4) * 8 + (lane & 7);
            int kc = (ks & 3) * 2 + ((lane >> 3) & 1);
            uint32_t off = (uint32_t)(rr * 128 + ((kc ^ (rr & 7)) << 4));
            ldsm4(b[g][0], b[g][1], b[g][2], b[g][3], sB + off);
        }
        #pragma unroll
        for (int mt = 0; mt < 4; mt++)
            #pragma unroll
            for (int nt = 0; nt < 8; nt++)
                mma_f16(acc[mt][nt], a[mt],
                        b[nt >> 1][(nt & 1) * 2], b[nt >> 1][(nt & 1) * 2 + 1]);
    }

    #pragma unroll
    for (int mt = 0; mt < 4; mt++) {
        int row = m0 + wm * 64 + mt * 16 + (lane >> 2);
        #pragma unroll
        for (int nt = 0; nt < 8; nt++) {
            int col = n0 + wn * 64 + nt * 8 + (lane & 3) * 2;
            *(float2*)(C + (size_t)row * NN + col) =
                make_float2(acc[mt][nt][0], acc[mt][nt][1]);
            *(float2*)(C + (size_t)(row + 8) * NN + col) =
                make_float2(acc[mt][nt][2], acc[mt][nt][3]);
        }
    }
}

// ---------------- launch ----------------
static inline void* sym_addr(const void* sym) {
    void* p = nullptr;
    cudaGetSymbolAddress(&p, sym);
    return p;
}

extern "C" void kernel_launch(void* const* d_in, const int* in_sizes, int n_in,
                              void* d_out, int out_size)
{
    const float* adj = (const float*)d_in[0];
    const float* x   = (const float*)d_in[1];
    const float* W1  = (const float*)d_in[2];
    const float* W2  = (const float*)d_in[3];
    const float* Wm1 = (const float*)d_in[4];
    const float* Wm2 = (const float*)d_in[5];
    const float* Wm3 = (const float*)d_in[6];
    const float* Wt  = (const float*)d_in[7];
    const float* bt  = (const float*)d_in[8];

    float* out = (float*)d_out;
    float* out_pred = out;
    float* out_x1   = out + (size_t)NN * NN;
    float* out_x2   = out_x1 + (size_t)NN * H1;
    float* out_z    = out_x2 + (size_t)NN * H2;

    float* t1 = (float*)sym_addr(g_t1);
    float* t2 = (float*)sym_addr(g_t2);
    float* tm = (float*)sym_addr(g_tm);
    __nv_bfloat16* xh  = (__nv_bfloat16*)sym_addr(g_xh);
    __nv_bfloat16* xl  = (__nv_bfloat16*)sym_addr(g_xl);
    __nv_bfloat16* x1h = (__nv_bfloat16*)sym_addr(g_x1h);
    __nv_bfloat16* x1l = (__nv_bfloat16*)sym_addr(g_x1l);
    __nv_bfloat16* x2h = (__nv_bfloat16*)sym_addr(g_x2h);
    __nv_bfloat16* x2l = (__nv_bfloat16*)sym_addr(g_x2l);
    __nv_bfloat16* zh  = (__nv_bfloat16*)sym_addr(g_zh);
    __nv_bfloat16* zl  = (__nv_bfloat16*)sym_addr(g_zl);
    __half* zf  = (__half*)sym_addr(g_zf);
    __half* tzf = (__half*)sym_addr(g_tzf);
    __nv_bfloat16* W1h = (__nv_bfloat16*)sym_addr(g_W1h);
    __nv_bfloat16* W1l = (__nv_bfloat16*)sym_addr(g_W1l);
    __nv_bfloat16* W2h = (__nv_bfloat16*)sym_addr(g_W2h);
    __nv_bfloat16* W2l = (__nv_bfloat16*)sym_addr(g_W2l);
    __nv_bfloat16* Wmh = (__nv_bfloat16*)sym_addr(g_Wmh);
    __nv_bfloat16* Wml = (__nv_bfloat16*)sym_addr(g_Wml);
    __nv_bfloat16* Wth = (__nv_bfloat16*)sym_addr(g_Wth);
    __nv_bfloat16* Wtl = (__nv_bfloat16*)sym_addr(g_Wtl);

    cudaFuncSetAttribute((const void*)gemm3<0>,
                         cudaFuncAttributeMaxDynamicSharedMemorySize, SMEM_BYTES);
    cudaFuncSetAttribute((const void*)gemm3<1>,
                         cudaFuncAttributeMaxDynamicSharedMemorySize, SMEM_BYTES);
    cudaFuncSetAttribute((const void*)t1_csr_kernel,
                         cudaFuncAttributeMaxDynamicSharedMemorySize, SMEM_BYTES);
    cudaFuncSetAttribute((const void*)pred_f16,
                         cudaFuncAttributeMaxDynamicSharedMemorySize, PF_SMEM);

    // 0. merged split of all static inputs (single launch)
    {
        SplitArgs a;
        const float* srcs[NSEG] = {x, W1, W2, Wm1, Wm2, Wm3, Wt};
        __nv_bfloat16* his[NSEG] = {xh, W1h, W2h, Wmh, Wmh + 64 * H2, Wmh + 128 * H2, Wth};
        __nv_bfloat16* los[NSEG] = {xl, W1l, W2l, Wml, Wml + 64 * H2, Wml + 128 * H2, Wtl};
        int ns[NSEG] = {NN * IN_DIM / 4, H1 * IN_DIM / 4, H2 * H1 / 4,
                        64 * H2 / 4, 64 * H2 / 4, 64 * H2 / 4, ZD * ZD / 4};
        int off = 0;
        for (int s = 0; s < NSEG; s++) {
            a.src[s] = (const float4*)srcs[s];
            a.hi[s]  = (uint32_t*)his[s];
            a.lo[s]  = (uint32_t*)los[s];
            a.nq[s]  = ns[s];
            a.blk_off[s] = off;
            off += (ns[s] + 255) / 256;
        }
        a.blk_off[NSEG] = off;
        split_all_kernel<<<off, 256>>>(a);
    }

    // 1. fused: t1 = x @ W1^T  (512 gemm tiles)  +  CSR build (2048 scan blocks)
    t1_csr_kernel<<<FUSE_BLOCKS, 128, SMEM_BYTES>>>(
        adj, xh, xl, W1h, W1l, t1);

    // x1 = relu(adj@t1) -> planes; out_x1 = sigmoid
    spmm4_kernel<1><<<NN / 4, 512>>>(
        (const float4*)t1, H1 / 4, 4, (float4*)out_x1,
        (uint2*)x1h, (uint2*)x1l, nullptr);
    // t2 = x1 @ W2^T
    gemm3<0><<<dim3(H2 / GBN, NN / GBM), 128, SMEM_BYTES>>>(
        x1h, x1l, W2h, W2l, nullptr, t2, nullptr, NN, H2, H1, H2);
    // x2 planes + sigmoid
    spmm4_kernel<1><<<NN / 8, 512>>>(
        (const float4*)t2, H2 / 4, 8, (float4*)out_x2,
        (uint2*)x2h, (uint2*)x2l, nullptr);
    // tm = x2 @ Wm^T
    gemm3<0><<<dim3(ZD / GBN, NN / GBM), 128, SMEM_BYTES>>>(
        x2h, x2l, Wmh, Wml, nullptr, tm, nullptr, NN, ZD, H2, ZD);
    // z = adj @ tm -> fp32 out + bf16 planes + fp16 plane
    spmm4_kernel<0><<<NN / 16, 768>>>(
        (const float4*)tm, ZD / 4, 16, (float4*)out_z,
        (uint2*)zh, (uint2*)zl, (uint2*)zf);
    // tz = leaky(z @ Wt^T + bt) -> fp16 plane only
    gemm3<1><<<dim3(ZD / GBN, NN / GBM), 128, SMEM_BYTES>>>(
        zh, zl, Wth, Wtl, bt, nullptr, tzf, NN, ZD, ZD, ZD);
    // pred = zf @ tzf^T  (fp16 single pass)
    pred_f16<<<dim3(NN / 128, NN / 128), 128, PF_SMEM>>>(zf, tzf, out_pred);

    (void)in_sizes; (void)n_in; (void)out_size;
}

// round 14
// speedup vs baseline: 1.4468x; 1.3641x over previous
#include <cuda_runtime.h>
#include <cuda_bf16.h>
#include <cuda_fp16.h>
#include <math.h>
#include <stdint.h>

// Problem dims
#define NN      8192
#define IN_DIM  1024
#define H1      512
#define H2      256
#define ZD      192
#define CAP     192

// ---------------- device scratch ----------------
__device__ float g_t1[NN * H1];
__device__ float g_t2[NN * H2];
__device__ float g_tm[NN * ZD];
__device__ __nv_bfloat16 g_xh [NN * IN_DIM];
__device__ __nv_bfloat16 g_xl [NN * IN_DIM];
__device__ __nv_bfloat16 g_x1h[NN * H1];
__device__ __nv_bfloat16 g_x1l[NN * H1];
__device__ __nv_bfloat16 g_x2h[NN * H2];
__device__ __nv_bfloat16 g_x2l[NN * H2];
__device__ __nv_bfloat16 g_zh [NN * ZD];
__device__ __nv_bfloat16 g_zl [NN * ZD];
__device__ __half        g_zf [NN * ZD];
__device__ __half        g_tzf[NN * ZD];
__device__ __nv_bfloat16 g_W1h[H1 * IN_DIM];
__device__ __nv_bfloat16 g_W1l[H1 * IN_DIM];
__device__ __nv_bfloat16 g_W2h[H2 * H1];
__device__ __nv_bfloat16 g_W2l[H2 * H1];
__device__ __nv_bfloat16 g_Wmh[ZD * H2];
__device__ __nv_bfloat16 g_Wml[ZD * H2];
__device__ __nv_bfloat16 g_Wth[ZD * ZD];
__device__ __nv_bfloat16 g_Wtl[ZD * ZD];
__device__ float g_vals[NN * CAP];
__device__ int   g_cols[NN * CAP];
__device__ int   g_cnt [NN];

// ---------------- helpers ----------------
__device__ __forceinline__ void split2(float v0, float v1, uint32_t& hi, uint32_t& lo) {
    __nv_bfloat16 h0 = __float2bfloat16_rn(v0);
    __nv_bfloat16 h1 = __float2bfloat16_rn(v1);
    __nv_bfloat16 l0 = __float2bfloat16_rn(v0 - __bfloat162float(h0));
    __nv_bfloat16 l1 = __float2bfloat16_rn(v1 - __bfloat162float(h1));
    hi = (uint32_t)__bfloat16_as_ushort(h0) | ((uint32_t)__bfloat16_as_ushort(h1) << 16);
    lo = (uint32_t)__bfloat16_as_ushort(l0) | ((uint32_t)__bfloat16_as_ushort(l1) << 16);
}

__device__ __forceinline__ uint32_t h2_as_u32(__half2 h) {
    uint32_t u;
    memcpy(&u, &h, 4);
    return u;
}

__device__ __forceinline__ void ldsm4(uint32_t& r0, uint32_t& r1, uint32_t& r2,
                                      uint32_t& r3, uint32_t addr) {
    asm volatile("ldmatrix.sync.aligned.m8n8.x4.shared.b16 {%0,%1,%2,%3}, [%4];"
                 : "=r"(r0), "=r"(r1), "=r"(r2), "=r"(r3) : "r"(addr));
}

__device__ __forceinline__ void mma_bf16(float (&d)[4], const uint32_t (&a)[4],
                                         uint32_t b0, uint32_t b1) {
    asm volatile(
        "mma.sync.aligned.m16n8k16.row.col.f32.bf16.bf16.f32 "
        "{%0,%1,%2,%3}, {%4,%5,%6,%7}, {%8,%9}, {%0,%1,%2,%3};"
        : "+f"(d[0]), "+f"(d[1]), "+f"(d[2]), "+f"(d[3])
        : "r"(a[0]), "r"(a[1]), "r"(a[2]), "r"(a[3]), "r"(b0), "r"(b1));
}

__device__ __forceinline__ void mma_f16(float (&d)[4], const uint32_t (&a)[4],
                                        uint32_t b0, uint32_t b1) {
    asm volatile(
        "mma.sync.aligned.m16n8k16.row.col.f32.f16.f16.f32 "
        "{%0,%1,%2,%3}, {%4,%5,%6,%7}, {%8,%9}, {%0,%1,%2,%3};"
        : "+f"(d[0]), "+f"(d[1]), "+f"(d[2]), "+f"(d[3])
        : "r"(a[0]), "r"(a[1]), "r"(a[2]), "r"(a[3]), "r"(b0), "r"(b1));
}

__device__ __forceinline__ void cp16(uint32_t dst, const void* src, bool v) {
    int sz = v ? 16 : 0;
    asm volatile("cp.async.cg.shared.global [%0], [%1], 16, %2;\n"
                 :: "r"(dst), "l"(src), "r"(sz) : "memory");
}
__device__ __forceinline__ void cp_commit() {
    asm volatile("cp.async.commit_group;" ::: "memory");
}
template <int n>
__device__ __forceinline__ void cp_wait() {
    asm volatile("cp.async.wait_group %0;" :: "n"(n) : "memory");
}

// ---------------- merged split: fp32 -> bf16 hi/lo planes, 7 segments ----------------
#define NSEG 7
struct SplitArgs {
    const float4* src[NSEG];
    uint32_t*     hi [NSEG];
    uint32_t*     lo [NSEG];
    int blk_off[NSEG + 1];
    int nq[NSEG];
};

__global__ void __launch_bounds__(256) split_all_kernel(SplitArgs a) {
    int b = blockIdx.x;
    int s = 0;
    #pragma unroll
    for (int k = 1; k < NSEG; k++)
        if (b >= a.blk_off[k]) s = k;
    int i = (b - a.blk_off[s]) * 256 + threadIdx.x;
    if (i >= a.nq[s]) return;
    float4 v = a.src[s][i];
    uint32_t h0, l0, h1, l1;
    split2(v.x, v.y, h0, l0);
    split2(v.z, v.w, h1, l1);
    a.hi[s][i * 2]     = h0; a.hi[s][i * 2 + 1] = h1;
    a.lo[s][i * 2]     = l0; a.lo[s][i * 2 + 1] = l1;
}

// ---------------- CSR build ----------------
__global__ void build_csr_kernel(const float* __restrict__ adj) {
    int row  = blockIdx.x * (blockDim.x >> 5) + (threadIdx.x >> 5);
    int lane = threadIdx.x & 31;
    if (row >= NN) return;
    const float* arow = adj + (size_t)row * NN;
    int cnt = 0;
    for (int c0 = 0; c0 < NN; c0 += 128) {
        float4 v = *(const float4*)(arow + c0 + lane * 4);
        unsigned m = (v.x != 0.f ? 1u : 0u) | (v.y != 0.f ? 2u : 0u)
                   | (v.z != 0.f ? 4u : 0u) | (v.w != 0.f ? 8u : 0u);
        int c = __popc(m);
        int s = c;
        #pragma unroll
        for (int d = 1; d < 32; d <<= 1) {
            int t = __shfl_up_sync(0xffffffffu, s, d);
            if (lane >= d) s += t;
        }
        int pos = cnt + s - c;
        int base = c0 + lane * 4;
        float vv[4] = {v.x, v.y, v.z, v.w};
        #pragma unroll
        for (int e = 0; e < 4; e++) {
            if ((m >> e) & 1u) {
                if (pos < CAP) {
                    g_cols[row * CAP + pos] = base + e;
                    g_vals[row * CAP + pos] = vv[e];
                }
                pos++;
            }
        }
        cnt += __shfl_sync(0xffffffffu, s, 31);
    }
    if (lane == 0) g_cnt[row] = (cnt < CAP) ? cnt : CAP;
}

// ---------------- SpMM, float4-vectorized, unroll-8 gathers ----------------
// Each thread owns 4 consecutive columns of one row. ncq = ncols/4.
// 8 independent gathers in flight per iteration; 4 accumulators (a0..a3 get
// j,j+4 / j+1,j+5 / ...). Remainder: one 4-group then singles.
template <int MODE>
__global__ void __launch_bounds__(256) spmm4_kernel(
    const float4* __restrict__ X, int ncq, int rpc,
    float4* __restrict__ out_f32,
    uint2* __restrict__ hi, uint2* __restrict__ lo,
    uint2* __restrict__ f16out)
{
    int t = threadIdx.x;
    int r = t / ncq;
    int c = t - r * ncq;
    int row = blockIdx.x * rpc + r;
    if (r >= rpc || row >= NN) return;

    int cnt = g_cnt[row];
    const int*   cols = g_cols + row * CAP;
    const float* vals = g_vals + row * CAP;

    float4 a0 = {0,0,0,0}, a1 = {0,0,0,0}, a2 = {0,0,0,0}, a3 = {0,0,0,0};
    int j = 0;
    for (; j + 8 <= cnt; j += 8) {
        int   c0 = cols[j+0], c1 = cols[j+1], c2 = cols[j+2], c3 = cols[j+3];
        int   c4 = cols[j+4], c5 = cols[j+5], c6 = cols[j+6], c7 = cols[j+7];
        float v0 = vals[j+0], v1 = vals[j+1], v2 = vals[j+2], v3 = vals[j+3];
        float v4 = vals[j+4], v5 = vals[j+5], v6 = vals[j+6], v7 = vals[j+7];
        float4 x0 = X[(size_t)c0 * ncq + c];
        float4 x1 = X[(size_t)c1 * ncq + c];
        float4 x2 = X[(size_t)c2 * ncq + c];
        float4 x3 = X[(size_t)c3 * ncq + c];
        float4 x4 = X[(size_t)c4 * ncq + c];
        float4 x5 = X[(size_t)c5 * ncq + c];
        float4 x6 = X[(size_t)c6 * ncq + c];
        float4 x7 = X[(size_t)c7 * ncq + c];
        a0.x += v0 * x0.x; a0.y += v0 * x0.y; a0.z += v0 * x0.z; a0.w += v0 * x0.w;
        a1.x += v1 * x1.x; a1.y += v1 * x1.y; a1.z += v1 * x1.z; a1.w += v1 * x1.w;
        a2.x += v2 * x2.x; a2.y += v2 * x2.y; a2.z += v2 * x2.z; a2.w += v2 * x2.w;
        a3.x += v3 * x3.x; a3.y += v3 * x3.y; a3.z += v3 * x3.z; a3.w += v3 * x3.w;
        a0.x += v4 * x4.x; a0.y += v4 * x4.y; a0.z += v4 * x4.z; a0.w += v4 * x4.w;
        a1.x += v5 * x5.x; a1.y += v5 * x5.y; a1.z += v5 * x5.z; a1.w += v5 * x5.w;
        a2.x += v6 * x6.x; a2.y += v6 * x6.y; a2.z += v6 * x6.z; a2.w += v6 * x6.w;
        a3.x += v7 * x7.x; a3.y += v7 * x7.y; a3.z += v7 * x7.z; a3.w += v7 * x7.w;
    }
    if (j + 4 <= cnt) {
        int   c0 = cols[j+0], c1 = cols[j+1], c2 = cols[j+2], c3 = cols[j+3];
        float v0 = vals[j+0], v1 = vals[j+1], v2 = vals[j+2], v3 = vals[j+3];
        float4 x0 = X[(size_t)c0 * ncq + c];
        float4 x1 = X[(size_t)c1 * ncq + c];
        float4 x2 = X[(size_t)c2 * ncq + c];
        float4 x3 = X[(size_t)c3 * ncq + c];
        a0.x += v0 * x0.x; a0.y += v0 * x0.y; a0.z += v0 * x0.z; a0.w += v0 * x0.w;
        a1.x += v1 * x1.x; a1.y += v1 * x1.y; a1.z += v1 * x1.z; a1.w += v1 * x1.w;
        a2.x += v2 * x2.x; a2.y += v2 * x2.y; a2.z += v2 * x2.z; a2.w += v2 * x2.w;
        a3.x += v3 * x3.x; a3.y += v3 * x3.y; a3.z += v3 * x3.z; a3.w += v3 * x3.w;
        j += 4;
    }
    for (; j < cnt; j++) {
        float v = vals[j];
        float4 xv = X[(size_t)cols[j] * ncq + c];
        a0.x += v * xv.x; a0.y += v * xv.y; a0.z += v * xv.z; a0.w += v * xv.w;
    }
    float4 acc;
    acc.x = (a0.x + a1.x) + (a2.x + a3.x);
    acc.y = (a0.y + a1.y) + (a2.y + a3.y);
    acc.z = (a0.z + a1.z) + (a2.z + a3.z);
    acc.w = (a0.w + a1.w) + (a2.w + a3.w);

    size_t o = (size_t)row * ncq + c;
    float4 rr;
    if (MODE == 1) {
        rr.x = acc.x > 0.f ? acc.x : 0.f;
        rr.y = acc.y > 0.f ? acc.y : 0.f;
        rr.z = acc.z > 0.f ? acc.z : 0.f;
        rr.w = acc.w > 0.f ? acc.w : 0.f;
    } else {
        rr = acc;
    }
    uint2 h, l;
    split2(rr.x, rr.y, h.x, l.x);
    split2(rr.z, rr.w, h.y, l.y);
    hi[o] = h;
    lo[o] = l;
    if (MODE == 0) {
        uint2 f;
        f.x = h2_as_u32(__floats2half2_rn(rr.x, rr.y));
        f.y = h2_as_u32(__floats2half2_rn(rr.z, rr.w));
        f16out[o] = f;
        out_f32[o] = acc;
    } else {
        float4 s;
        s.x = 1.0f / (1.0f + __expf(-rr.x));
        s.y = 1.0f / (1.0f + __expf(-rr.y));
        s.z = 1.0f / (1.0f + __expf(-rr.z));
        s.w = 1.0f / (1.0f + __expf(-rr.w));
        out_f32[o] = s;
    }
}

// ---------------- bf16x3 mma.sync GEMM, 128x64 tiles (round-10 proven) ----------------
#define GBM 128
#define GBN 64
#define GBK 32
#define STG_BYTES 24576
#define NSTAGE 3
#define SMEM_BYTES (NSTAGE * STG_BYTES)
#define PL_AH 0
#define PL_AL 8192
#define PL_BH 16384
#define PL_BL 20480

__device__ __forceinline__ uint32_t sw_off(int r, int kc) {
    return (uint32_t)(r * 64 + ((kc ^ ((r >> 1) & 3)) << 4));
}

// EPI 0: fp32 store. EPI 1: +bias, leaky_relu(0.1) -> fp16 plane only.
template <int EPI>
__global__ void __launch_bounds__(128, 3) gemm3(
    const __nv_bfloat16* __restrict__ Ah, const __nv_bfloat16* __restrict__ Al,
    const __nv_bfloat16* __restrict__ Bh, const __nv_bfloat16* __restrict__ Bl,
    const float* __restrict__ bias, float* __restrict__ C,
    __half* __restrict__ Cf,
    int M, int N, int K, int ldc)
{
    extern __shared__ uint8_t smem[];
    const uint32_t sbase = (uint32_t)__cvta_generic_to_shared(smem);

    const int tid  = threadIdx.x;
    const int lane = tid & 31;
    const int wid  = tid >> 5;
    const int wm   = wid & 1;
    const int wn   = wid >> 1;
    const int m0   = blockIdx.y * GBM;
    const int n0   = blockIdx.x * GBN;

    float acc[4][4][4];
    #pragma unroll
    for (int i = 0; i < 4; i++)
        #pragma unroll
        for (int j = 0; j < 4; j++)
            #pragma unroll
            for (int q = 0; q < 4; q++) acc[i][j][q] = 0.f;

    auto load_tile = [&](int it, int s) {
        int k0 = it * GBK;
        uint32_t st = sbase + s * STG_BYTES;
        #pragma unroll
        for (int i = 0; i < 4; i++) {
            int f = tid + i * 128;
            int r = f >> 2, c = f & 3;
            uint32_t doff = sw_off(r, c);
            size_t aoff = (size_t)(m0 + r) * K + k0 + c * 8;
            cp16(st + PL_AH + doff, Ah + aoff, true);
            cp16(st + PL_AL + doff, Al + aoff, true);
        }
        #pragma unroll
        for (int i = 0; i < 2; i++) {
            int f = tid + i * 128;
            int r = f >> 2, c = f & 3;
            uint32_t doff = sw_off(r, c);
            bool bv = (n0 + r) < N;
            int  br = bv ? (n0 + r) : 0;
            size_t boff = (size_t)br * K + k0 + c * 8;
            cp16(st + PL_BH + doff, Bh + boff, bv);
            cp16(st + PL_BL + doff, Bl + boff, bv);
        }
        cp_commit();
    };

    const int nIt = K / GBK;
    load_tile(0, 0);
    if (nIt > 1) load_tile(1, 1);

    for (int it = 0; it < nIt; it++) {
        if (it + 1 < nIt) cp_wait<1>(); else cp_wait<0>();
        __syncthreads();
        if (it + 2 < nIt) load_tile(it + 2, (it + 2) % NSTAGE);

        uint32_t st = sbase + (it % NSTAGE) * STG_BYTES;
        #pragma unroll
        for (int ks = 0; ks < 2; ks++) {
            uint32_t ah[4][4], al[4][4], bh[2][4], bl[2][4];
            #pragma unroll
            for (int g = 0; g < 2; g++) {
                int rr = wn * 32 + g * 16 + (lane >> 4) * 8 + (lane & 7);
                int kc = ks * 2 + ((lane >> 3) & 1);
                uint32_t off = sw_off(rr, kc);
                ldsm4(bh[g][0], bh[g][1], bh[g][2], bh[g][3], st + PL_BH + off);
                ldsm4(bl[g][0], bl[g][1], bl[g][2], bl[g][3], st + PL_BL + off);
            }
            #pragma unroll
            for (int mt = 0; mt < 4; mt++) {
                int rr = wm * 64 + mt * 16 + ((lane >> 3) & 1) * 8 + (lane & 7);
                int kc = ks * 2 + (lane >> 4);
                uint32_t off = sw_off(rr, kc);
                ldsm4(ah[mt][0], ah[mt][1], ah[mt][2], ah[mt][3], st + PL_AH + off);
                ldsm4(al[mt][0], al[mt][1], al[mt][2], al[mt][3], st + PL_AL + off);
            }
            #pragma unroll
            for (int mt = 0; mt < 4; mt++)
                #pragma unroll
                for (int nt = 0; nt < 4; nt++) {
                    uint32_t b0 = bh[nt >> 1][(nt & 1) * 2];
                    uint32_t b1 = bh[nt >> 1][(nt & 1) * 2 + 1];
                    mma_bf16(acc[mt][nt], ah[mt], b0, b1);
                    mma_bf16(acc[mt][nt], al[mt], b0, b1);
                    mma_bf16(acc[mt][nt], ah[mt],
                             bl[nt >> 1][(nt & 1) * 2], bl[nt >> 1][(nt & 1) * 2 + 1]);
                }
        }
        __syncthreads();
    }

    #pragma unroll
    for (int mt = 0; mt < 4; mt++) {
        int row = m0 + wm * 64 + mt * 16 + (lane >> 2);
        #pragma unroll
        for (int nt = 0; nt < 4; nt++) {
            int col = n0 + wn * 32 + nt * 8 + (lane & 3) * 2;
            if (col < N) {
                float c0 = acc[mt][nt][0], c1 = acc[mt][nt][1];
                float c2 = acc[mt][nt][2], c3 = acc[mt][nt][3];
                if (EPI == 1) {
                    float b0 = bias[col], b1 = bias[col + 1];
                    c0 += b0; c1 += b1; c2 += b0; c3 += b1;
                    c0 = (c0 >= 0.f) ? c0 : 0.1f * c0;
                    c1 = (c1 >= 0.f) ? c1 : 0.1f * c1;
                    c2 = (c2 >= 0.f) ? c2 : 0.1f * c2;
                    c3 = (c3 >= 0.f) ? c3 : 0.1f * c3;
                    *(__half2*)(Cf + (size_t)row * ldc + col)       = __floats2half2_rn(c0, c1);
                    *(__half2*)(Cf + (size_t)(row + 8) * ldc + col) = __floats2half2_rn(c2, c3);
                } else {
                    *(float2*)(C + (size_t)row * ldc + col)       = make_float2(c0, c1);
                    *(float2*)(C + (size_t)(row + 8) * ldc + col) = make_float2(c2, c3);
                }
            }
        }
    }
}

// ---------------- fp16 single-pass pred kernel ----------------
#define PF_SMEM 98304

__global__ void __launch_bounds__(128, 2) pred_f16(
    const __half* __restrict__ Af, const __half* __restrict__ Bf,
    float* __restrict__ C)
{
    extern __shared__ uint8_t smem[];
    const uint32_t sbase = (uint32_t)__cvta_generic_to_shared(smem);
    const int tid  = threadIdx.x;
    const int lane = tid & 31;
    const int wid  = tid >> 5;
    const int wm   = wid & 1;
    const int wn   = wid >> 1;
    const int m0   = blockIdx.y * 128;
    const int n0   = blockIdx.x * 128;

    #pragma unroll
    for (int i = 0; i < 24; i++) {
        int f = tid + i * 128;
        int r = f / 24, c = f % 24;
        int sub = c >> 3, cc = c & 7;
        uint32_t doff = (uint32_t)(sub * 16384 + r * 128 + ((cc ^ (r & 7)) << 4));
        cp16(sbase + doff,         Af + (size_t)(m0 + r) * ZD + c * 8, true);
        cp16(sbase + 49152 + doff, Bf + (size_t)(n0 + r) * ZD + c * 8, true);
    }
    cp_commit();
    cp_wait<0>();
    __syncthreads();

    float acc[4][8][4];
    #pragma unroll
    for (int i = 0; i < 4; i++)
        #pragma unroll
        for (int j = 0; j < 8; j++)
            #pragma unroll
            for (int q = 0; q < 4; q++) acc[i][j][q] = 0.f;

    #pragma unroll
    for (int ks = 0; ks < 12; ks++) {
        int sub = ks >> 2;
        uint32_t sA = sbase + sub * 16384;
        uint32_t sB = sbase + 49152 + sub * 16384;
        uint32_t a[4][4], b[4][4];
        #pragma unroll
        for (int mt = 0; mt < 4; mt++) {
            int rr = wm * 64 + mt * 16 + ((lane >> 3) & 1) * 8 + (lane & 7);
            int kc = (ks & 3) * 2 + (lane >> 4);
            uint32_t off = (uint32_t)(rr * 128 + ((kc ^ (rr & 7)) << 4));
            ldsm4(a[mt][0], a[mt][1], a[mt][2], a[mt][3], sA + off);
        }
        #pragma unroll
        for (int g = 0; g < 4; g++) {
            int rr = wn * 64 + g * 16 + (lane >> 4) * 8 + (lane & 7);
            int kc = (ks & 3) * 2 + ((lane >> 3) & 1);
            uint32_t off = (uint32_t)(rr * 128 + ((kc ^ (rr & 7)) << 4));
            ldsm4(b[g][0], b[g][1], b[g][2], b[g][3], sB + off);
        }
        #pragma unroll
        for (int mt = 0; mt < 4; mt++)
            #pragma unroll
            for (int nt = 0; nt < 8; nt++)
                mma_f16(acc[mt][nt], a[mt],
                        b[nt >> 1][(nt & 1) * 2], b[nt >> 1][(nt & 1) * 2 + 1]);
    }

    #pragma unroll
    for (int mt = 0; mt < 4; mt++) {
        int row = m0 + wm * 64 + mt * 16 + (lane >> 2);
        #pragma unroll
        for (int nt = 0; nt < 8; nt++) {
            int col = n0 + wn * 64 + nt * 8 + (lane & 3) * 2;
            *(float2*)(C + (size_t)row * NN + col) =
                make_float2(acc[mt][nt][0], acc[mt][nt][1]);
            *(float2*)(C + (size_t)(row + 8) * NN + col) =
                make_float2(acc[mt][nt][2], acc[mt][nt][3]);
        }
    }
}

// ---------------- launch ----------------
static inline void* sym_addr(const void* sym) {
    void* p = nullptr;
    cudaGetSymbolAddress(&p, sym);
    return p;
}

extern "C" void kernel_launch(void* const* d_in, const int* in_sizes, int n_in,
                              void* d_out, int out_size)
{
    const float* adj = (const float*)d_in[0];
    const float* x   = (const float*)d_in[1];
    const float* W1  = (const float*)d_in[2];
    const float* W2  = (const float*)d_in[3];
    const float* Wm1 = (const float*)d_in[4];
    const float* Wm2 = (const float*)d_in[5];
    const float* Wm3 = (const float*)d_in[6];
    const float* Wt  = (const float*)d_in[7];
    const float* bt  = (const float*)d_in[8];

    float* out = (float*)d_out;
    float* out_pred = out;
    float* out_x1   = out + (size_t)NN * NN;
    float* out_x2   = out_x1 + (size_t)NN * H1;
    float* out_z    = out_x2 + (size_t)NN * H2;

    float* t1 = (float*)sym_addr(g_t1);
    float* t2 = (float*)sym_addr(g_t2);
    float* tm = (float*)sym_addr(g_tm);
    __nv_bfloat16* xh  = (__nv_bfloat16*)sym_addr(g_xh);
    __nv_bfloat16* xl  = (__nv_bfloat16*)sym_addr(g_xl);
    __nv_bfloat16* x1h = (__nv_bfloat16*)sym_addr(g_x1h);
    __nv_bfloat16* x1l = (__nv_bfloat16*)sym_addr(g_x1l);
    __nv_bfloat16* x2h = (__nv_bfloat16*)sym_addr(g_x2h);
    __nv_bfloat16* x2l = (__nv_bfloat16*)sym_addr(g_x2l);
    __nv_bfloat16* zh  = (__nv_bfloat16*)sym_addr(g_zh);
    __nv_bfloat16* zl  = (__nv_bfloat16*)sym_addr(g_zl);
    __half* zf  = (__half*)sym_addr(g_zf);
    __half* tzf = (__half*)sym_addr(g_tzf);
    __nv_bfloat16* W1h = (__nv_bfloat16*)sym_addr(g_W1h);
    __nv_bfloat16* W1l = (__nv_bfloat16*)sym_addr(g_W1l);
    __nv_bfloat16* W2h = (__nv_bfloat16*)sym_addr(g_W2h);
    __nv_bfloat16* W2l = (__nv_bfloat16*)sym_addr(g_W2l);
    __nv_bfloat16* Wmh = (__nv_bfloat16*)sym_addr(g_Wmh);
    __nv_bfloat16* Wml = (__nv_bfloat16*)sym_addr(g_Wml);
    __nv_bfloat16* Wth = (__nv_bfloat16*)sym_addr(g_Wth);
    __nv_bfloat16* Wtl = (__nv_bfloat16*)sym_addr(g_Wtl);

    cudaFuncSetAttribute((const void*)gemm3<0>,
                         cudaFuncAttributeMaxDynamicSharedMemorySize, SMEM_BYTES);
    cudaFuncSetAttribute((const void*)gemm3<1>,
                         cudaFuncAttributeMaxDynamicSharedMemorySize, SMEM_BYTES);
    cudaFuncSetAttribute((const void*)pred_f16,
                         cudaFuncAttributeMaxDynamicSharedMemorySize, PF_SMEM);

    // 0. merged split of all static inputs (single launch)
    {
        SplitArgs a;
        const float* srcs[NSEG] = {x, W1, W2, Wm1, Wm2, Wm3, Wt};
        __nv_bfloat16* his[NSEG] = {xh, W1h, W2h, Wmh, Wmh + 64 * H2, Wmh + 128 * H2, Wth};
        __nv_bfloat16* los[NSEG] = {xl, W1l, W2l, Wml, Wml + 64 * H2, Wml + 128 * H2, Wtl};
        int ns[NSEG] = {NN * IN_DIM / 4, H1 * IN_DIM / 4, H2 * H1 / 4,
                        64 * H2 / 4, 64 * H2 / 4, 64 * H2 / 4, ZD * ZD / 4};
        int off = 0;
        for (int s = 0; s < NSEG; s++) {
            a.src[s] = (const float4*)srcs[s];
            a.hi[s]  = (uint32_t*)his[s];
            a.lo[s]  = (uint32_t*)los[s];
            a.nq[s]  = ns[s];
            a.blk_off[s] = off;
            off += (ns[s] + 255) / 256;
        }
        a.blk_off[NSEG] = off;
        split_all_kernel<<<off, 256>>>(a);
    }

    build_csr_kernel<<<NN / 8, 256>>>(adj);

    // t1 = x @ W1^T
    gemm3<0><<<dim3(H1 / GBN, NN / GBM), 128, SMEM_BYTES>>>(
        xh, xl, W1h, W1l, nullptr, t1, nullptr, NN, H1, IN_DIM, H1);
    // x1 = relu(adj@t1) -> planes; out_x1 = sigmoid   (ncq=128, rpc=2, 256 thr)
    spmm4_kernel<1><<<NN / 2, 256>>>(
        (const float4*)t1, H1 / 4, 2, (float4*)out_x1,
        (uint2*)x1h, (uint2*)x1l, nullptr);
    // t2 = x1 @ W2^T
    gemm3<0><<<dim3(H2 / GBN, NN / GBM), 128, SMEM_BYTES>>>(
        x1h, x1l, W2h, W2l, nullptr, t2, nullptr, NN, H2, H1, H2);
    // x2 planes + sigmoid   (ncq=64, rpc=4)
    spmm4_kernel<1><<<NN / 4, 256>>>(
        (const float4*)t2, H2 / 4, 4, (float4*)out_x2,
        (uint2*)x2h, (uint2*)x2l, nullptr);
    // tm = x2 @ Wm^T
    gemm3<0><<<dim3(ZD / GBN, NN / GBM), 128, SMEM_BYTES>>>(
        x2h, x2l, Wmh, Wml, nullptr, tm, nullptr, NN, ZD, H2, ZD);
    // z = adj @ tm -> fp32 out + bf16 planes + fp16 plane  (ncq=48, rpc=5)
    spmm4_kernel<0><<<(NN + 4) / 5, 256>>>(
        (const float4*)tm, ZD / 4, 5, (float4*)out_z,
        (uint2*)zh, (uint2*)zl, (uint2*)zf);
    // tz = leaky(z @ Wt^T + bt) -> fp16 plane only
    gemm3<1><<<dim3(ZD / GBN, NN / GBM), 128, SMEM_BYTES>>>(
        zh, zl, Wth, Wtl, bt, nullptr, tzf, NN, ZD, ZD, ZD);
    // pred = zf @ tzf^T  (fp16 single pass)
    pred_f16<<<dim3(NN / 128, NN / 128), 128, PF_SMEM>>>(zf, tzf, out_pred);

    (void)in_sizes; (void)n_in; (void)out_size;
}

// round 15
// speedup vs baseline: 1.4648x; 1.0124x over previous
#include <cuda_runtime.h>
#include <cuda_bf16.h>
#include <cuda_fp16.h>
#include <math.h>
#include <stdint.h>

// Problem dims
#define NN      8192
#define IN_DIM  1024
#define H1      512
#define H2      256
#define ZD      192
#define CAP     192

// ---------------- device scratch ----------------
__device__ float g_t1[NN * H1];
__device__ float g_t2[NN * H2];
__device__ float g_tm[NN * ZD];
__device__ __nv_bfloat16 g_xh [NN * IN_DIM];
__device__ __nv_bfloat16 g_xl [NN * IN_DIM];
__device__ __nv_bfloat16 g_x1h[NN * H1];
__device__ __nv_bfloat16 g_x1l[NN * H1];
__device__ __nv_bfloat16 g_x2h[NN * H2];
__device__ __nv_bfloat16 g_x2l[NN * H2];
__device__ __nv_bfloat16 g_zh [NN * ZD];
__device__ __nv_bfloat16 g_zl [NN * ZD];
__device__ __half        g_zf [NN * ZD];
__device__ __half        g_tzf[NN * ZD];
__device__ __nv_bfloat16 g_W1h[H1 * IN_DIM];
__device__ __nv_bfloat16 g_W1l[H1 * IN_DIM];
__device__ __nv_bfloat16 g_W2h[H2 * H1];
__device__ __nv_bfloat16 g_W2l[H2 * H1];
__device__ __nv_bfloat16 g_Wmh[ZD * H2];
__device__ __nv_bfloat16 g_Wml[ZD * H2];
__device__ __nv_bfloat16 g_Wth[ZD * ZD];
__device__ __nv_bfloat16 g_Wtl[ZD * ZD];
__device__ float g_vals[NN * CAP];
__device__ int   g_cols[NN * CAP];
__device__ int   g_cnt [NN];

// ---------------- helpers ----------------
__device__ __forceinline__ void split2(float v0, float v1, uint32_t& hi, uint32_t& lo) {
    __nv_bfloat16 h0 = __float2bfloat16_rn(v0);
    __nv_bfloat16 h1 = __float2bfloat16_rn(v1);
    __nv_bfloat16 l0 = __float2bfloat16_rn(v0 - __bfloat162float(h0));
    __nv_bfloat16 l1 = __float2bfloat16_rn(v1 - __bfloat162float(h1));
    hi = (uint32_t)__bfloat16_as_ushort(h0) | ((uint32_t)__bfloat16_as_ushort(h1) << 16);
    lo = (uint32_t)__bfloat16_as_ushort(l0) | ((uint32_t)__bfloat16_as_ushort(l1) << 16);
}

__device__ __forceinline__ uint32_t h2_as_u32(__half2 h) {
    uint32_t u;
    memcpy(&u, &h, 4);
    return u;
}

__device__ __forceinline__ void ldsm4(uint32_t& r0, uint32_t& r1, uint32_t& r2,
                                      uint32_t& r3, uint32_t addr) {
    asm volatile("ldmatrix.sync.aligned.m8n8.x4.shared.b16 {%0,%1,%2,%3}, [%4];"
                 : "=r"(r0), "=r"(r1), "=r"(r2), "=r"(r3) : "r"(addr));
}

__device__ __forceinline__ void mma_bf16(float (&d)[4], const uint32_t (&a)[4],
                                         uint32_t b0, uint32_t b1) {
    asm volatile(
        "mma.sync.aligned.m16n8k16.row.col.f32.bf16.bf16.f32 "
        "{%0,%1,%2,%3}, {%4,%5,%6,%7}, {%8,%9}, {%0,%1,%2,%3};"
        : "+f"(d[0]), "+f"(d[1]), "+f"(d[2]), "+f"(d[3])
        : "r"(a[0]), "r"(a[1]), "r"(a[2]), "r"(a[3]), "r"(b0), "r"(b1));
}

__device__ __forceinline__ void mma_f16(float (&d)[4], const uint32_t (&a)[4],
                                        uint32_t b0, uint32_t b1) {
    asm volatile(
        "mma.sync.aligned.m16n8k16.row.col.f32.f16.f16.f32 "
        "{%0,%1,%2,%3}, {%4,%5,%6,%7}, {%8,%9}, {%0,%1,%2,%3};"
        : "+f"(d[0]), "+f"(d[1]), "+f"(d[2]), "+f"(d[3])
        : "r"(a[0]), "r"(a[1]), "r"(a[2]), "r"(a[3]), "r"(b0), "r"(b1));
}

__device__ __forceinline__ void cp16(uint32_t dst, const void* src, bool v) {
    int sz = v ? 16 : 0;
    asm volatile("cp.async.cg.shared.global [%0], [%1], 16, %2;\n"
                 :: "r"(dst), "l"(src), "r"(sz) : "memory");
}
__device__ __forceinline__ void cp_commit() {
    asm volatile("cp.async.commit_group;" ::: "memory");
}
template <int n>
__device__ __forceinline__ void cp_wait() {
    asm volatile("cp.async.wait_group %0;" :: "n"(n) : "memory");
}

// ---------------- merged split: fp32 -> bf16 hi/lo planes, 7 segments ----------------
#define NSEG 7
struct SplitArgs {
    const float4* src[NSEG];
    uint32_t*     hi [NSEG];
    uint32_t*     lo [NSEG];
    int blk_off[NSEG + 1];
    int nq[NSEG];
};

__global__ void __launch_bounds__(256) split_all_kernel(SplitArgs a) {
    int b = blockIdx.x;
    int s = 0;
    #pragma unroll
    for (int k = 1; k < NSEG; k++)
        if (b >= a.blk_off[k]) s = k;
    int i = (b - a.blk_off[s]) * 256 + threadIdx.x;
    if (i >= a.nq[s]) return;
    float4 v = a.src[s][i];
    uint32_t h0, l0, h1, l1;
    split2(v.x, v.y, h0, l0);
    split2(v.z, v.w, h1, l1);
    a.hi[s][i * 2]     = h0; a.hi[s][i * 2 + 1] = h1;
    a.lo[s][i * 2]     = l0; a.lo[s][i * 2 + 1] = l1;
}

// ---------------- CSR build ----------------
__global__ void build_csr_kernel(const float* __restrict__ adj) {
    int row  = blockIdx.x * (blockDim.x >> 5) + (threadIdx.x >> 5);
    int lane = threadIdx.x & 31;
    if (row >= NN) return;
    const float* arow = adj + (size_t)row * NN;
    int cnt = 0;
    for (int c0 = 0; c0 < NN; c0 += 128) {
        float4 v = *(const float4*)(arow + c0 + lane * 4);
        unsigned m = (v.x != 0.f ? 1u : 0u) | (v.y != 0.f ? 2u : 0u)
                   | (v.z != 0.f ? 4u : 0u) | (v.w != 0.f ? 8u : 0u);
        int c = __popc(m);
        int s = c;
        #pragma unroll
        for (int d = 1; d < 32; d <<= 1) {
            int t = __shfl_up_sync(0xffffffffu, s, d);
            if (lane >= d) s += t;
        }
        int pos = cnt + s - c;
        int base = c0 + lane * 4;
        float vv[4] = {v.x, v.y, v.z, v.w};
        #pragma unroll
        for (int e = 0; e < 4; e++) {
            if ((m >> e) & 1u) {
                if (pos < CAP) {
                    g_cols[row * CAP + pos] = base + e;
                    g_vals[row * CAP + pos] = vv[e];
                }
                pos++;
            }
        }
        cnt += __shfl_sync(0xffffffffu, s, 31);
    }
    if (lane == 0) g_cnt[row] = (cnt < CAP) ? cnt : CAP;
}

// ---------------- SpMM, float4-vectorized, unroll-8 gathers (round-14, at LTS cap) ----
template <int MODE>
__global__ void __launch_bounds__(256) spmm4_kernel(
    const float4* __restrict__ X, int ncq, int rpc,
    float4* __restrict__ out_f32,
    uint2* __restrict__ hi, uint2* __restrict__ lo,
    uint2* __restrict__ f16out)
{
    int t = threadIdx.x;
    int r = t / ncq;
    int c = t - r * ncq;
    int row = blockIdx.x * rpc + r;
    if (r >= rpc || row >= NN) return;

    int cnt = g_cnt[row];
    const int*   cols = g_cols + row * CAP;
    const float* vals = g_vals + row * CAP;

    float4 a0 = {0,0,0,0}, a1 = {0,0,0,0}, a2 = {0,0,0,0}, a3 = {0,0,0,0};
    int j = 0;
    for (; j + 8 <= cnt; j += 8) {
        int   c0 = cols[j+0], c1 = cols[j+1], c2 = cols[j+2], c3 = cols[j+3];
        int   c4 = cols[j+4], c5 = cols[j+5], c6 = cols[j+6], c7 = cols[j+7];
        float v0 = vals[j+0], v1 = vals[j+1], v2 = vals[j+2], v3 = vals[j+3];
        float v4 = vals[j+4], v5 = vals[j+5], v6 = vals[j+6], v7 = vals[j+7];
        float4 x0 = X[(size_t)c0 * ncq + c];
        float4 x1 = X[(size_t)c1 * ncq + c];
        float4 x2 = X[(size_t)c2 * ncq + c];
        float4 x3 = X[(size_t)c3 * ncq + c];
        float4 x4 = X[(size_t)c4 * ncq + c];
        float4 x5 = X[(size_t)c5 * ncq + c];
        float4 x6 = X[(size_t)c6 * ncq + c];
        float4 x7 = X[(size_t)c7 * ncq + c];
        a0.x += v0 * x0.x; a0.y += v0 * x0.y; a0.z += v0 * x0.z; a0.w += v0 * x0.w;
        a1.x += v1 * x1.x; a1.y += v1 * x1.y; a1.z += v1 * x1.z; a1.w += v1 * x1.w;
        a2.x += v2 * x2.x; a2.y += v2 * x2.y; a2.z += v2 * x2.z; a2.w += v2 * x2.w;
        a3.x += v3 * x3.x; a3.y += v3 * x3.y; a3.z += v3 * x3.z; a3.w += v3 * x3.w;
        a0.x += v4 * x4.x; a0.y += v4 * x4.y; a0.z += v4 * x4.z; a0.w += v4 * x4.w;
        a1.x += v5 * x5.x; a1.y += v5 * x5.y; a1.z += v5 * x5.z; a1.w += v5 * x5.w;
        a2.x += v6 * x6.x; a2.y += v6 * x6.y; a2.z += v6 * x6.z; a2.w += v6 * x6.w;
        a3.x += v7 * x7.x; a3.y += v7 * x7.y; a3.z += v7 * x7.z; a3.w += v7 * x7.w;
    }
    if (j + 4 <= cnt) {
        int   c0 = cols[j+0], c1 = cols[j+1], c2 = cols[j+2], c3 = cols[j+3];
        float v0 = vals[j+0], v1 = vals[j+1], v2 = vals[j+2], v3 = vals[j+3];
        float4 x0 = X[(size_t)c0 * ncq + c];
        float4 x1 = X[(size_t)c1 * ncq + c];
        float4 x2 = X[(size_t)c2 * ncq + c];
        float4 x3 = X[(size_t)c3 * ncq + c];
        a0.x += v0 * x0.x; a0.y += v0 * x0.y; a0.z += v0 * x0.z; a0.w += v0 * x0.w;
        a1.x += v1 * x1.x; a1.y += v1 * x1.y; a1.z += v1 * x1.z; a1.w += v1 * x1.w;
        a2.x += v2 * x2.x; a2.y += v2 * x2.y; a2.z += v2 * x2.z; a2.w += v2 * x2.w;
        a3.x += v3 * x3.x; a3.y += v3 * x3.y; a3.z += v3 * x3.z; a3.w += v3 * x3.w;
        j += 4;
    }
    for (; j < cnt; j++) {
        float v = vals[j];
        float4 xv = X[(size_t)cols[j] * ncq + c];
        a0.x += v * xv.x; a0.y += v * xv.y; a0.z += v * xv.z; a0.w += v * xv.w;
    }
    float4 acc;
    acc.x = (a0.x + a1.x) + (a2.x + a3.x);
    acc.y = (a0.y + a1.y) + (a2.y + a3.y);
    acc.z = (a0.z + a1.z) + (a2.z + a3.z);
    acc.w = (a0.w + a1.w) + (a2.w + a3.w);

    size_t o = (size_t)row * ncq + c;
    float4 rr;
    if (MODE == 1) {
        rr.x = acc.x > 0.f ? acc.x : 0.f;
        rr.y = acc.y > 0.f ? acc.y : 0.f;
        rr.z = acc.z > 0.f ? acc.z : 0.f;
        rr.w = acc.w > 0.f ? acc.w : 0.f;
    } else {
        rr = acc;
    }
    uint2 h, l;
    split2(rr.x, rr.y, h.x, l.x);
    split2(rr.z, rr.w, h.y, l.y);
    hi[o] = h;
    lo[o] = l;
    if (MODE == 0) {
        uint2 f;
        f.x = h2_as_u32(__floats2half2_rn(rr.x, rr.y));
        f.y = h2_as_u32(__floats2half2_rn(rr.z, rr.w));
        f16out[o] = f;
        out_f32[o] = acc;
    } else {
        float4 s;
        s.x = 1.0f / (1.0f + __expf(-rr.x));
        s.y = 1.0f / (1.0f + __expf(-rr.y));
        s.z = 1.0f / (1.0f + __expf(-rr.z));
        s.w = 1.0f / (1.0f + __expf(-rr.w));
        out_f32[o] = s;
    }
}

// ---------------- bf16x3 mma.sync GEMM, 128x64 tiles, 4 CTAs/SM ----------------
// 2-stage cp.async (48KB/CTA x 4 CTAs = 192KB), per-mt A fragment loading to
// shrink live regs (~120) -> __launch_bounds__(128,4) = 16 warps/SM; t1's 512
// CTAs fit one wave (592 slots).
#define GBM 128
#define GBN 64
#define GBK 32
#define STG_BYTES 24576
#define NSTAGE 2
#define SMEM_BYTES (NSTAGE * STG_BYTES)
#define PL_AH 0
#define PL_AL 8192
#define PL_BH 16384
#define PL_BL 20480

__device__ __forceinline__ uint32_t sw_off(int r, int kc) {
    return (uint32_t)(r * 64 + ((kc ^ ((r >> 1) & 3)) << 4));
}

// EPI 0: fp32 store. EPI 1: +bias, leaky_relu(0.1) -> fp16 plane only.
template <int EPI>
__global__ void __launch_bounds__(128, 4) gemm3(
    const __nv_bfloat16* __restrict__ Ah, const __nv_bfloat16* __restrict__ Al,
    const __nv_bfloat16* __restrict__ Bh, const __nv_bfloat16* __restrict__ Bl,
    const float* __restrict__ bias, float* __restrict__ C,
    __half* __restrict__ Cf,
    int M, int N, int K, int ldc)
{
    extern __shared__ uint8_t smem[];
    const uint32_t sbase = (uint32_t)__cvta_generic_to_shared(smem);

    const int tid  = threadIdx.x;
    const int lane = tid & 31;
    const int wid  = tid >> 5;
    const int wm   = wid & 1;
    const int wn   = wid >> 1;
    const int m0   = blockIdx.y * GBM;
    const int n0   = blockIdx.x * GBN;

    float acc[4][4][4];
    #pragma unroll
    for (int i = 0; i < 4; i++)
        #pragma unroll
        for (int j = 0; j < 4; j++)
            #pragma unroll
            for (int q = 0; q < 4; q++) acc[i][j][q] = 0.f;

    auto load_tile = [&](int it, int s) {
        int k0 = it * GBK;
        uint32_t st = sbase + s * STG_BYTES;
        #pragma unroll
        for (int i = 0; i < 4; i++) {
            int f = tid + i * 128;
            int r = f >> 2, c = f & 3;
            uint32_t doff = sw_off(r, c);
            size_t aoff = (size_t)(m0 + r) * K + k0 + c * 8;
            cp16(st + PL_AH + doff, Ah + aoff, true);
            cp16(st + PL_AL + doff, Al + aoff, true);
        }
        #pragma unroll
        for (int i = 0; i < 2; i++) {
            int f = tid + i * 128;
            int r = f >> 2, c = f & 3;
            uint32_t doff = sw_off(r, c);
            bool bv = (n0 + r) < N;
            int  br = bv ? (n0 + r) : 0;
            size_t boff = (size_t)br * K + k0 + c * 8;
            cp16(st + PL_BH + doff, Bh + boff, bv);
            cp16(st + PL_BL + doff, Bl + boff, bv);
        }
        cp_commit();
    };

    const int nIt = K / GBK;
    load_tile(0, 0);

    for (int it = 0; it < nIt; it++) {
        if (it + 1 < nIt) {
            load_tile(it + 1, (it + 1) & 1);
            cp_wait<1>();
        } else {
            cp_wait<0>();
        }
        __syncthreads();

        uint32_t st = sbase + (it & 1) * STG_BYTES;
        #pragma unroll
        for (int ks = 0; ks < 2; ks++) {
            uint32_t bh[2][4], bl[2][4];
            #pragma unroll
            for (int g = 0; g < 2; g++) {
                int rr = wn * 32 + g * 16 + (lane >> 4) * 8 + (lane & 7);
                int kc = ks * 2 + ((lane >> 3) & 1);
                uint32_t off = sw_off(rr, kc);
                ldsm4(bh[g][0], bh[g][1], bh[g][2], bh[g][3], st + PL_BH + off);
                ldsm4(bl[g][0], bl[g][1], bl[g][2], bl[g][3], st + PL_BL + off);
            }
            // per-mt A fragments: only 8 A regs live at a time
            #pragma unroll
            for (int mt = 0; mt < 4; mt++) {
                uint32_t ah[4], al[4];
                int rr = wm * 64 + mt * 16 + ((lane >> 3) & 1) * 8 + (lane & 7);
                int kc = ks * 2 + (lane >> 4);
                uint32_t off = sw_off(rr, kc);
                ldsm4(ah[0], ah[1], ah[2], ah[3], st + PL_AH + off);
                ldsm4(al[0], al[1], al[2], al[3], st + PL_AL + off);
                #pragma unroll
                for (int nt = 0; nt < 4; nt++) {
                    uint32_t b0 = bh[nt >> 1][(nt & 1) * 2];
                    uint32_t b1 = bh[nt >> 1][(nt & 1) * 2 + 1];
                    mma_bf16(acc[mt][nt], ah, b0, b1);
                    mma_bf16(acc[mt][nt], al, b0, b1);
                    mma_bf16(acc[mt][nt], ah,
                             bl[nt >> 1][(nt & 1) * 2], bl[nt >> 1][(nt & 1) * 2 + 1]);
                }
            }
        }
        __syncthreads();
    }

    #pragma unroll
    for (int mt = 0; mt < 4; mt++) {
        int row = m0 + wm * 64 + mt * 16 + (lane >> 2);
        #pragma unroll
        for (int nt = 0; nt < 4; nt++) {
            int col = n0 + wn * 32 + nt * 8 + (lane & 3) * 2;
            if (col < N) {
                float c0 = acc[mt][nt][0], c1 = acc[mt][nt][1];
                float c2 = acc[mt][nt][2], c3 = acc[mt][nt][3];
                if (EPI == 1) {
                    float b0 = bias[col], b1 = bias[col + 1];
                    c0 += b0; c1 += b1; c2 += b0; c3 += b1;
                    c0 = (c0 >= 0.f) ? c0 : 0.1f * c0;
                    c1 = (c1 >= 0.f) ? c1 : 0.1f * c1;
                    c2 = (c2 >= 0.f) ? c2 : 0.1f * c2;
                    c3 = (c3 >= 0.f) ? c3 : 0.1f * c3;
                    *(__half2*)(Cf + (size_t)row * ldc + col)       = __floats2half2_rn(c0, c1);
                    *(__half2*)(Cf + (size_t)(row + 8) * ldc + col) = __floats2half2_rn(c2, c3);
                } else {
                    *(float2*)(C + (size_t)row * ldc + col)       = make_float2(c0, c1);
                    *(float2*)(C + (size_t)(row + 8) * ldc + col) = make_float2(c2, c3);
                }
            }
        }
    }
}

// ---------------- fp16 single-pass pred kernel ----------------
#define PF_SMEM 98304

__global__ void __launch_bounds__(128, 2) pred_f16(
    const __half* __restrict__ Af, const __half* __restrict__ Bf,
    float* __restrict__ C)
{
    extern __shared__ uint8_t smem[];
    const uint32_t sbase = (uint32_t)__cvta_generic_to_shared(smem);
    const int tid  = threadIdx.x;
    const int lane = tid & 31;
    const int wid  = tid >> 5;
    const int wm   = wid & 1;
    const int wn   = wid >> 1;
    const int m0   = blockIdx.y * 128;
    const int n0   = blockIdx.x * 128;

    #pragma unroll
    for (int i = 0; i < 24; i++) {
        int f = tid + i * 128;
        int r = f / 24, c = f % 24;
        int sub = c >> 3, cc = c & 7;
        uint32_t doff = (uint32_t)(sub * 16384 + r * 128 + ((cc ^ (r & 7)) << 4));
        cp16(sbase + doff,         Af + (size_t)(m0 + r) * ZD + c * 8, true);
        cp16(sbase + 49152 + doff, Bf + (size_t)(n0 + r) * ZD + c * 8, true);
    }
    cp_commit();
    cp_wait<0>();
    __syncthreads();

    float acc[4][8][4];
    #pragma unroll
    for (int i = 0; i < 4; i++)
        #pragma unroll
        for (int j = 0; j < 8; j++)
            #pragma unroll
            for (int q = 0; q < 4; q++) acc[i][j][q] = 0.f;

    #pragma unroll
    for (int ks = 0; ks < 12; ks++) {
        int sub = ks >> 2;
        uint32_t sA = sbase + sub * 16384;
        uint32_t sB = sbase + 49152 + sub * 16384;
        uint32_t a[4][4], b[4][4];
        #pragma unroll
        for (int mt = 0; mt < 4; mt++) {
            int rr = wm * 64 + mt * 16 + ((lane >> 3) & 1) * 8 + (lane & 7);
            int kc = (ks & 3) * 2 + (lane >> 4);
            uint32_t off = (uint32_t)(rr * 128 + ((kc ^ (rr & 7)) << 4));
            ldsm4(a[mt][0], a[mt][1], a[mt][2], a[mt][3], sA + off);
        }
        #pragma unroll
        for (int g = 0; g < 4; g++) {
            int rr = wn * 64 + g * 16 + (lane >> 4) * 8 + (lane & 7);
            int kc = (ks & 3) * 2 + ((lane >> 3) & 1);
            uint32_t off = (uint32_t)(rr * 128 + ((kc ^ (rr & 7)) << 4));
            ldsm4(b[g][0], b[g][1], b[g][2], b[g][3], sB + off);
        }
        #pragma unroll
        for (int mt = 0; mt < 4; mt++)
            #pragma unroll
            for (int nt = 0; nt < 8; nt++)
                mma_f16(acc[mt][nt], a[mt],
                        b[nt >> 1][(nt & 1) * 2], b[nt >> 1][(nt & 1) * 2 + 1]);
    }

    #pragma unroll
    for (int mt = 0; mt < 4; mt++) {
        int row = m0 + wm * 64 + mt * 16 + (lane >> 2);
        #pragma unroll
        for (int nt = 0; nt < 8; nt++) {
            int col = n0 + wn * 64 + nt * 8 + (lane & 3) * 2;
            *(float2*)(C + (size_t)row * NN + col) =
                make_float2(acc[mt][nt][0], acc[mt][nt][1]);
            *(float2*)(C + (size_t)(row + 8) * NN + col) =
                make_float2(acc[mt][nt][2], acc[mt][nt][3]);
        }
    }
}

// ---------------- launch ----------------
static inline void* sym_addr(const void* sym) {
    void* p = nullptr;
    cudaGetSymbolAddress(&p, sym);
    return p;
}

extern "C" void kernel_launch(void* const* d_in, const int* in_sizes, int n_in,
                              void* d_out, int out_size)
{
    const float* adj = (const float*)d_in[0];
    const float* x   = (const float*)d_in[1];
    const float* W1  = (const float*)d_in[2];
    const float* W2  = (const float*)d_in[3];
    const float* Wm1 = (const float*)d_in[4];
    const float* Wm2 = (const float*)d_in[5];
    const float* Wm3 = (const float*)d_in[6];
    const float* Wt  = (const float*)d_in[7];
    const float* bt  = (const float*)d_in[8];

    float* out = (float*)d_out;
    float* out_pred = out;
    float* out_x1   = out + (size_t)NN * NN;
    float* out_x2   = out_x1 + (size_t)NN * H1;
    float* out_z    = out_x2 + (size_t)NN * H2;

    float* t1 = (float*)sym_addr(g_t1);
    float* t2 = (float*)sym_addr(g_t2);
    float* tm = (float*)sym_addr(g_tm);
    __nv_bfloat16* xh  = (__nv_bfloat16*)sym_addr(g_xh);
    __nv_bfloat16* xl  = (__nv_bfloat16*)sym_addr(g_xl);
    __nv_bfloat16* x1h = (__nv_bfloat16*)sym_addr(g_x1h);
    __nv_bfloat16* x1l = (__nv_bfloat16*)sym_addr(g_x1l);
    __nv_bfloat16* x2h = (__nv_bfloat16*)sym_addr(g_x2h);
    __nv_bfloat16* x2l = (__nv_bfloat16*)sym_addr(g_x2l);
    __nv_bfloat16* zh  = (__nv_bfloat16*)sym_addr(g_zh);
    __nv_bfloat16* zl  = (__nv_bfloat16*)sym_addr(g_zl);
    __half* zf  = (__half*)sym_addr(g_zf);
    __half* tzf = (__half*)sym_addr(g_tzf);
    __nv_bfloat16* W1h = (__nv_bfloat16*)sym_addr(g_W1h);
    __nv_bfloat16* W1l = (__nv_bfloat16*)sym_addr(g_W1l);
    __nv_bfloat16* W2h = (__nv_bfloat16*)sym_addr(g_W2h);
    __nv_bfloat16* W2l = (__nv_bfloat16*)sym_addr(g_W2l);
    __nv_bfloat16* Wmh = (__nv_bfloat16*)sym_addr(g_Wmh);
    __nv_bfloat16* Wml = (__nv_bfloat16*)sym_addr(g_Wml);
    __nv_bfloat16* Wth = (__nv_bfloat16*)sym_addr(g_Wth);
    __nv_bfloat16* Wtl = (__nv_bfloat16*)sym_addr(g_Wtl);

    cudaFuncSetAttribute((const void*)gemm3<0>,
                         cudaFuncAttributeMaxDynamicSharedMemorySize, SMEM_BYTES);
    cudaFuncSetAttribute((const void*)gemm3<1>,
                         cudaFuncAttributeMaxDynamicSharedMemorySize, SMEM_BYTES);
    cudaFuncSetAttribute((const void*)pred_f16,
                         cudaFuncAttributeMaxDynamicSharedMemorySize, PF_SMEM);

    // 0. merged split of all static inputs (single launch)
    {
        SplitArgs a;
        const float* srcs[NSEG] = {x, W1, W2, Wm1, Wm2, Wm3, Wt};
        __nv_bfloat16* his[NSEG] = {xh, W1h, W2h, Wmh, Wmh + 64 * H2, Wmh + 128 * H2, Wth};
        __nv_bfloat16* los[NSEG] = {xl, W1l, W2l, Wml, Wml + 64 * H2, Wml + 128 * H2, Wtl};
        int ns[NSEG] = {NN * IN_DIM / 4, H1 * IN_DIM / 4, H2 * H1 / 4,
                        64 * H2 / 4, 64 * H2 / 4, 64 * H2 / 4, ZD * ZD / 4};
        int off = 0;
        for (int s = 0; s < NSEG; s++) {
            a.src[s] = (const float4*)srcs[s];
            a.hi[s]  = (uint32_t*)his[s];
            a.lo[s]  = (uint32_t*)los[s];
            a.nq[s]  = ns[s];
            a.blk_off[s] = off;
            off += (ns[s] + 255) / 256;
        }
        a.blk_off[NSEG] = off;
        split_all_kernel<<<off, 256>>>(a);
    }

    build_csr_kernel<<<NN / 8, 256>>>(adj);

    // t1 = x @ W1^T   (512 CTAs, one wave at 4 CTAs/SM)
    gemm3<0><<<dim3(H1 / GBN, NN / GBM), 128, SMEM_BYTES>>>(
        xh, xl, W1h, W1l, nullptr, t1, nullptr, NN, H1, IN_DIM, H1);
    // x1 = relu(adj@t1) -> planes; out_x1 = sigmoid
    spmm4_kernel<1><<<NN / 2, 256>>>(
        (const float4*)t1, H1 / 4, 2, (float4*)out_x1,
        (uint2*)x1h, (uint2*)x1l, nullptr);
    // t2 = x1 @ W2^T
    gemm3<0><<<dim3(H2 / GBN, NN / GBM), 128, SMEM_BYTES>>>(
        x1h, x1l, W2h, W2l, nullptr, t2, nullptr, NN, H2, H1, H2);
    // x2 planes + sigmoid
    spmm4_kernel<1><<<NN / 4, 256>>>(
        (const float4*)t2, H2 / 4, 4, (float4*)out_x2,
        (uint2*)x2h, (uint2*)x2l, nullptr);
    // tm = x2 @ Wm^T
    gemm3<0><<<dim3(ZD / GBN, NN / GBM), 128, SMEM_BYTES>>>(
        x2h, x2l, Wmh, Wml, nullptr, tm, nullptr, NN, ZD, H2, ZD);
    // z = adj @ tm -> fp32 out + bf16 planes + fp16 plane
    spmm4_kernel<0><<<(NN + 4) / 5, 256>>>(
        (const float4*)tm, ZD / 4, 5, (float4*)out_z,
        (uint2*)zh, (uint2*)zl, (uint2*)zf);
    // tz = leaky(z @ Wt^T + bt) -> fp16 plane only
    gemm3<1><<<dim3(ZD / GBN, NN / GBM), 128, SMEM_BYTES>>>(
        zh, zl, Wth, Wtl, bt, nullptr, tzf, NN, ZD, ZD, ZD);
    // pred = zf @ tzf^T  (fp16 single pass)
    pred_f16<<<dim3(NN / 128, NN / 128), 128, PF_SMEM>>>(zf, tzf, out_pred);

    (void)in_sizes; (void)n_in; (void)out_size;
}

// round 16
// speedup vs baseline: 1.4981x; 1.0228x over previous
#include <cuda_runtime.h>
#include <cuda_bf16.h>
#include <cuda_fp16.h>
#include <math.h>
#include <stdint.h>

// Problem dims
#define NN      8192
#define IN_DIM  1024
#define H1      512
#define H2      256
#define ZD      192
#define CAP     192

// ---------------- device scratch ----------------
__device__ float g_t1[NN * H1];
__device__ float g_t2[NN * H2];
__device__ float g_tm[NN * ZD];
__device__ __nv_bfloat16 g_xh [NN * IN_DIM];
__device__ __nv_bfloat16 g_xl [NN * IN_DIM];
__device__ __nv_bfloat16 g_x1h[NN * H1];
__device__ __nv_bfloat16 g_x1l[NN * H1];
__device__ __nv_bfloat16 g_x2h[NN * H2];
__device__ __nv_bfloat16 g_x2l[NN * H2];
__device__ __nv_bfloat16 g_zh [NN * ZD];
__device__ __nv_bfloat16 g_zl [NN * ZD];
__device__ __half        g_zf [NN * ZD];
__device__ __half        g_tzf[NN * ZD];
__device__ __nv_bfloat16 g_W1h[H1 * IN_DIM];
__device__ __nv_bfloat16 g_W1l[H1 * IN_DIM];
__device__ __nv_bfloat16 g_W2h[H2 * H1];
__device__ __nv_bfloat16 g_W2l[H2 * H1];
__device__ __nv_bfloat16 g_Wmh[ZD * H2];
__device__ __nv_bfloat16 g_Wml[ZD * H2];
__device__ __nv_bfloat16 g_Wth[ZD * ZD];
__device__ __nv_bfloat16 g_Wtl[ZD * ZD];
__device__ float g_vals[NN * CAP];
__device__ int   g_cols[NN * CAP];
__device__ int   g_cnt [NN];

// ---------------- helpers ----------------
__device__ __forceinline__ void split2(float v0, float v1, uint32_t& hi, uint32_t& lo) {
    __nv_bfloat16 h0 = __float2bfloat16_rn(v0);
    __nv_bfloat16 h1 = __float2bfloat16_rn(v1);
    __nv_bfloat16 l0 = __float2bfloat16_rn(v0 - __bfloat162float(h0));
    __nv_bfloat16 l1 = __float2bfloat16_rn(v1 - __bfloat162float(h1));
    hi = (uint32_t)__bfloat16_as_ushort(h0) | ((uint32_t)__bfloat16_as_ushort(h1) << 16);
    lo = (uint32_t)__bfloat16_as_ushort(l0) | ((uint32_t)__bfloat16_as_ushort(l1) << 16);
}

__device__ __forceinline__ uint32_t h2_as_u32(__half2 h) {
    uint32_t u;
    memcpy(&u, &h, 4);
    return u;
}

__device__ __forceinline__ void ldsm4(uint32_t& r0, uint32_t& r1, uint32_t& r2,
                                      uint32_t& r3, uint32_t addr) {
    asm volatile("ldmatrix.sync.aligned.m8n8.x4.shared.b16 {%0,%1,%2,%3}, [%4];"
                 : "=r"(r0), "=r"(r1), "=r"(r2), "=r"(r3) : "r"(addr));
}

__device__ __forceinline__ void mma_bf16(float (&d)[4], const uint32_t (&a)[4],
                                         uint32_t b0, uint32_t b1) {
    asm volatile(
        "mma.sync.aligned.m16n8k16.row.col.f32.bf16.bf16.f32 "
        "{%0,%1,%2,%3}, {%4,%5,%6,%7}, {%8,%9}, {%0,%1,%2,%3};"
        : "+f"(d[0]), "+f"(d[1]), "+f"(d[2]), "+f"(d[3])
        : "r"(a[0]), "r"(a[1]), "r"(a[2]), "r"(a[3]), "r"(b0), "r"(b1));
}

__device__ __forceinline__ void mma_f16(float (&d)[4], const uint32_t (&a)[4],
                                        uint32_t b0, uint32_t b1) {
    asm volatile(
        "mma.sync.aligned.m16n8k16.row.col.f32.f16.f16.f32 "
        "{%0,%1,%2,%3}, {%4,%5,%6,%7}, {%8,%9}, {%0,%1,%2,%3};"
        : "+f"(d[0]), "+f"(d[1]), "+f"(d[2]), "+f"(d[3])
        : "r"(a[0]), "r"(a[1]), "r"(a[2]), "r"(a[3]), "r"(b0), "r"(b1));
}

__device__ __forceinline__ void cp16(uint32_t dst, const void* src, bool v) {
    int sz = v ? 16 : 0;
    asm volatile("cp.async.cg.shared.global [%0], [%1], 16, %2;\n"
                 :: "r"(dst), "l"(src), "r"(sz) : "memory");
}
__device__ __forceinline__ void cp_commit() {
    asm volatile("cp.async.commit_group;" ::: "memory");
}
template <int n>
__device__ __forceinline__ void cp_wait() {
    asm volatile("cp.async.wait_group %0;" :: "n"(n) : "memory");
}

// ---------------- merged split: fp32 -> bf16 hi/lo planes, 7 segments ----------------
#define NSEG 7
struct SplitArgs {
    const float4* src[NSEG];
    uint32_t*     hi [NSEG];
    uint32_t*     lo [NSEG];
    int blk_off[NSEG + 1];
    int nq[NSEG];
};

__global__ void __launch_bounds__(256) split_all_kernel(SplitArgs a) {
    int b = blockIdx.x;
    int s = 0;
    #pragma unroll
    for (int k = 1; k < NSEG; k++)
        if (b >= a.blk_off[k]) s = k;
    int i = (b - a.blk_off[s]) * 256 + threadIdx.x;
    if (i >= a.nq[s]) return;
    float4 v = a.src[s][i];
    uint32_t h0, l0, h1, l1;
    split2(v.x, v.y, h0, l0);
    split2(v.z, v.w, h1, l1);
    a.hi[s][i * 2]     = h0; a.hi[s][i * 2 + 1] = h1;
    a.lo[s][i * 2]     = l0; a.lo[s][i * 2 + 1] = l1;
}

// ---------------- CSR build ----------------
__global__ void build_csr_kernel(const float* __restrict__ adj) {
    int row  = blockIdx.x * (blockDim.x >> 5) + (threadIdx.x >> 5);
    int lane = threadIdx.x & 31;
    if (row >= NN) return;
    const float* arow = adj + (size_t)row * NN;
    int cnt = 0;
    for (int c0 = 0; c0 < NN; c0 += 128) {
        float4 v = *(const float4*)(arow + c0 + lane * 4);
        unsigned m = (v.x != 0.f ? 1u : 0u) | (v.y != 0.f ? 2u : 0u)
                   | (v.z != 0.f ? 4u : 0u) | (v.w != 0.f ? 8u : 0u);
        int c = __popc(m);
        int s = c;
        #pragma unroll
        for (int d = 1; d < 32; d <<= 1) {
            int t = __shfl_up_sync(0xffffffffu, s, d);
            if (lane >= d) s += t;
        }
        int pos = cnt + s - c;
        int base = c0 + lane * 4;
        float vv[4] = {v.x, v.y, v.z, v.w};
        #pragma unroll
        for (int e = 0; e < 4; e++) {
            if ((m >> e) & 1u) {
                if (pos < CAP) {
                    g_cols[row * CAP + pos] = base + e;
                    g_vals[row * CAP + pos] = vv[e];
                }
                pos++;
            }
        }
        cnt += __shfl_sync(0xffffffffu, s, 31);
    }
    if (lane == 0) g_cnt[row] = (cnt < CAP) ? cnt : CAP;
}

// ---------------- SpMM, float4-vectorized, unroll-8 gathers (at LTS cap) ----
template <int MODE>
__global__ void __launch_bounds__(256) spmm4_kernel(
    const float4* __restrict__ X, int ncq, int rpc,
    float4* __restrict__ out_f32,
    uint2* __restrict__ hi, uint2* __restrict__ lo,
    uint2* __restrict__ f16out)
{
    int t = threadIdx.x;
    int r = t / ncq;
    int c = t - r * ncq;
    int row = blockIdx.x * rpc + r;
    if (r >= rpc || row >= NN) return;

    int cnt = g_cnt[row];
    const int*   cols = g_cols + row * CAP;
    const float* vals = g_vals + row * CAP;

    float4 a0 = {0,0,0,0}, a1 = {0,0,0,0}, a2 = {0,0,0,0}, a3 = {0,0,0,0};
    int j = 0;
    for (; j + 8 <= cnt; j += 8) {
        int   c0 = cols[j+0], c1 = cols[j+1], c2 = cols[j+2], c3 = cols[j+3];
        int   c4 = cols[j+4], c5 = cols[j+5], c6 = cols[j+6], c7 = cols[j+7];
        float v0 = vals[j+0], v1 = vals[j+1], v2 = vals[j+2], v3 = vals[j+3];
        float v4 = vals[j+4], v5 = vals[j+5], v6 = vals[j+6], v7 = vals[j+7];
        float4 x0 = X[(size_t)c0 * ncq + c];
        float4 x1 = X[(size_t)c1 * ncq + c];
        float4 x2 = X[(size_t)c2 * ncq + c];
        float4 x3 = X[(size_t)c3 * ncq + c];
        float4 x4 = X[(size_t)c4 * ncq + c];
        float4 x5 = X[(size_t)c5 * ncq + c];
        float4 x6 = X[(size_t)c6 * ncq + c];
        float4 x7 = X[(size_t)c7 * ncq + c];
        a0.x += v0 * x0.x; a0.y += v0 * x0.y; a0.z += v0 * x0.z; a0.w += v0 * x0.w;
        a1.x += v1 * x1.x; a1.y += v1 * x1.y; a1.z += v1 * x1.z; a1.w += v1 * x1.w;
        a2.x += v2 * x2.x; a2.y += v2 * x2.y; a2.z += v2 * x2.z; a2.w += v2 * x2.w;
        a3.x += v3 * x3.x; a3.y += v3 * x3.y; a3.z += v3 * x3.z; a3.w += v3 * x3.w;
        a0.x += v4 * x4.x; a0.y += v4 * x4.y; a0.z += v4 * x4.z; a0.w += v4 * x4.w;
        a1.x += v5 * x5.x; a1.y += v5 * x5.y; a1.z += v5 * x5.z; a1.w += v5 * x5.w;
        a2.x += v6 * x6.x; a2.y += v6 * x6.y; a2.z += v6 * x6.z; a2.w += v6 * x6.w;
        a3.x += v7 * x7.x; a3.y += v7 * x7.y; a3.z += v7 * x7.z; a3.w += v7 * x7.w;
    }
    if (j + 4 <= cnt) {
        int   c0 = cols[j+0], c1 = cols[j+1], c2 = cols[j+2], c3 = cols[j+3];
        float v0 = vals[j+0], v1 = vals[j+1], v2 = vals[j+2], v3 = vals[j+3];
        float4 x0 = X[(size_t)c0 * ncq + c];
        float4 x1 = X[(size_t)c1 * ncq + c];
        float4 x2 = X[(size_t)c2 * ncq + c];
        float4 x3 = X[(size_t)c3 * ncq + c];
        a0.x += v0 * x0.x; a0.y += v0 * x0.y; a0.z += v0 * x0.z; a0.w += v0 * x0.w;
        a1.x += v1 * x1.x; a1.y += v1 * x1.y; a1.z += v1 * x1.z; a1.w += v1 * x1.w;
        a2.x += v2 * x2.x; a2.y += v2 * x2.y; a2.z += v2 * x2.z; a2.w += v2 * x2.w;
        a3.x += v3 * x3.x; a3.y += v3 * x3.y; a3.z += v3 * x3.z; a3.w += v3 * x3.w;
        j += 4;
    }
    for (; j < cnt; j++) {
        float v = vals[j];
        float4 xv = X[(size_t)cols[j] * ncq + c];
        a0.x += v * xv.x; a0.y += v * xv.y; a0.z += v * xv.z; a0.w += v * xv.w;
    }
    float4 acc;
    acc.x = (a0.x + a1.x) + (a2.x + a3.x);
    acc.y = (a0.y + a1.y) + (a2.y + a3.y);
    acc.z = (a0.z + a1.z) + (a2.z + a3.z);
    acc.w = (a0.w + a1.w) + (a2.w + a3.w);

    size_t o = (size_t)row * ncq + c;
    float4 rr;
    if (MODE == 1) {
        rr.x = acc.x > 0.f ? acc.x : 0.f;
        rr.y = acc.y > 0.f ? acc.y : 0.f;
        rr.z = acc.z > 0.f ? acc.z : 0.f;
        rr.w = acc.w > 0.f ? acc.w : 0.f;
    } else {
        rr = acc;
    }
    uint2 h, l;
    split2(rr.x, rr.y, h.x, l.x);
    split2(rr.z, rr.w, h.y, l.y);
    hi[o] = h;
    lo[o] = l;
    if (MODE == 0) {
        uint2 f;
        f.x = h2_as_u32(__floats2half2_rn(rr.x, rr.y));
        f.y = h2_as_u32(__floats2half2_rn(rr.z, rr.w));
        f16out[o] = f;
        out_f32[o] = acc;
    } else {
        float4 s;
        s.x = 1.0f / (1.0f + __expf(-rr.x));
        s.y = 1.0f / (1.0f + __expf(-rr.y));
        s.z = 1.0f / (1.0f + __expf(-rr.z));
        s.w = 1.0f / (1.0f + __expf(-rr.w));
        out_f32[o] = s;
    }
}

// ---------------- bf16x3 mma.sync GEMM, 128x64 tiles, 4 CTAs/SM ----------------
#define GBM 128
#define GBN 64
#define GBK 32
#define STG_BYTES 24576
#define NSTAGE 2
#define SMEM_BYTES (NSTAGE * STG_BYTES)
#define PL_AH 0
#define PL_AL 8192
#define PL_BH 16384
#define PL_BL 20480

__device__ __forceinline__ uint32_t sw_off(int r, int kc) {
    return (uint32_t)(r * 64 + ((kc ^ ((r >> 1) & 3)) << 4));
}

// EPI 0: fp32 store. EPI 1: +bias, leaky_relu(0.1) -> fp16 plane only.
template <int EPI>
__global__ void __launch_bounds__(128, 4) gemm3(
    const __nv_bfloat16* __restrict__ Ah, const __nv_bfloat16* __restrict__ Al,
    const __nv_bfloat16* __restrict__ Bh, const __nv_bfloat16* __restrict__ Bl,
    const float* __restrict__ bias, float* __restrict__ C,
    __half* __restrict__ Cf,
    int M, int N, int K, int ldc)
{
    extern __shared__ uint8_t smem[];
    const uint32_t sbase = (uint32_t)__cvta_generic_to_shared(smem);

    const int tid  = threadIdx.x;
    const int lane = tid & 31;
    const int wid  = tid >> 5;
    const int wm   = wid & 1;
    const int wn   = wid >> 1;
    const int m0   = blockIdx.y * GBM;
    const int n0   = blockIdx.x * GBN;

    float acc[4][4][4];
    #pragma unroll
    for (int i = 0; i < 4; i++)
        #pragma unroll
        for (int j = 0; j < 4; j++)
            #pragma unroll
            for (int q = 0; q < 4; q++) acc[i][j][q] = 0.f;

    auto load_tile = [&](int it, int s) {
        int k0 = it * GBK;
        uint32_t st = sbase + s * STG_BYTES;
        #pragma unroll
        for (int i = 0; i < 4; i++) {
            int f = tid + i * 128;
            int r = f >> 2, c = f & 3;
            uint32_t doff = sw_off(r, c);
            size_t aoff = (size_t)(m0 + r) * K + k0 + c * 8;
            cp16(st + PL_AH + doff, Ah + aoff, true);
            cp16(st + PL_AL + doff, Al + aoff, true);
        }
        #pragma unroll
        for (int i = 0; i < 2; i++) {
            int f = tid + i * 128;
            int r = f >> 2, c = f & 3;
            uint32_t doff = sw_off(r, c);
            bool bv = (n0 + r) < N;
            int  br = bv ? (n0 + r) : 0;
            size_t boff = (size_t)br * K + k0 + c * 8;
            cp16(st + PL_BH + doff, Bh + boff, bv);
            cp16(st + PL_BL + doff, Bl + boff, bv);
        }
        cp_commit();
    };

    const int nIt = K / GBK;
    load_tile(0, 0);

    for (int it = 0; it < nIt; it++) {
        if (it + 1 < nIt) {
            load_tile(it + 1, (it + 1) & 1);
            cp_wait<1>();
        } else {
            cp_wait<0>();
        }
        __syncthreads();

        uint32_t st = sbase + (it & 1) * STG_BYTES;
        #pragma unroll
        for (int ks = 0; ks < 2; ks++) {
            uint32_t bh[2][4], bl[2][4];
            #pragma unroll
            for (int g = 0; g < 2; g++) {
                int rr = wn * 32 + g * 16 + (lane >> 4) * 8 + (lane & 7);
                int kc = ks * 2 + ((lane >> 3) & 1);
                uint32_t off = sw_off(rr, kc);
                ldsm4(bh[g][0], bh[g][1], bh[g][2], bh[g][3], st + PL_BH + off);
                ldsm4(bl[g][0], bl[g][1], bl[g][2], bl[g][3], st + PL_BL + off);
            }
            #pragma unroll
            for (int mt = 0; mt < 4; mt++) {
                uint32_t ah[4], al[4];
                int rr = wm * 64 + mt * 16 + ((lane >> 3) & 1) * 8 + (lane & 7);
                int kc = ks * 2 + (lane >> 4);
                uint32_t off = sw_off(rr, kc);
                ldsm4(ah[0], ah[1], ah[2], ah[3], st + PL_AH + off);
                ldsm4(al[0], al[1], al[2], al[3], st + PL_AL + off);
                #pragma unroll
                for (int nt = 0; nt < 4; nt++) {
                    uint32_t b0 = bh[nt >> 1][(nt & 1) * 2];
                    uint32_t b1 = bh[nt >> 1][(nt & 1) * 2 + 1];
                    mma_bf16(acc[mt][nt], ah, b0, b1);
                    mma_bf16(acc[mt][nt], al, b0, b1);
                    mma_bf16(acc[mt][nt], ah,
                             bl[nt >> 1][(nt & 1) * 2], bl[nt >> 1][(nt & 1) * 2 + 1]);
                }
            }
        }
        __syncthreads();
    }

    #pragma unroll
    for (int mt = 0; mt < 4; mt++) {
        int row = m0 + wm * 64 + mt * 16 + (lane >> 2);
        #pragma unroll
        for (int nt = 0; nt < 4; nt++) {
            int col = n0 + wn * 32 + nt * 8 + (lane & 3) * 2;
            if (col < N) {
                float c0 = acc[mt][nt][0], c1 = acc[mt][nt][1];
                float c2 = acc[mt][nt][2], c3 = acc[mt][nt][3];
                if (EPI == 1) {
                    float b0 = bias[col], b1 = bias[col + 1];
                    c0 += b0; c1 += b1; c2 += b0; c3 += b1;
                    c0 = (c0 >= 0.f) ? c0 : 0.1f * c0;
                    c1 = (c1 >= 0.f) ? c1 : 0.1f * c1;
                    c2 = (c2 >= 0.f) ? c2 : 0.1f * c2;
                    c3 = (c3 >= 0.f) ? c3 : 0.1f * c3;
                    *(__half2*)(Cf + (size_t)row * ldc + col)       = __floats2half2_rn(c0, c1);
                    *(__half2*)(Cf + (size_t)(row + 8) * ldc + col) = __floats2half2_rn(c2, c3);
                } else {
                    *(float2*)(C + (size_t)row * ldc + col)       = make_float2(c0, c1);
                    *(float2*)(C + (size_t)(row + 8) * ldc + col) = make_float2(c2, c3);
                }
            }
        }
    }
}

// ---------------- fp16 single-pass pred kernel, sub-tile pipelined loads -------
// K=192 panel split into 3 sub-tiles, each its own cp.async commit group;
// waits interleave with compute so sub1/sub2 loads fly under sub0/sub1 MMAs.
#define PF_SMEM 98304

__global__ void __launch_bounds__(128, 2) pred_f16(
    const __half* __restrict__ Af, const __half* __restrict__ Bf,
    float* __restrict__ C)
{
    extern __shared__ uint8_t smem[];
    const uint32_t sbase = (uint32_t)__cvta_generic_to_shared(smem);
    const int tid  = threadIdx.x;
    const int lane = tid & 31;
    const int wid  = tid >> 5;
    const int wm   = wid & 1;
    const int wn   = wid >> 1;
    const int m0   = blockIdx.y * 128;
    const int n0   = blockIdx.x * 128;

    // load one K-sub-tile (64 cols) of both A and B panels; own commit group
    auto load_sub = [&](int sub) {
        #pragma unroll
        for (int i = 0; i < 8; i++) {
            int f = tid + i * 128;           // 0..1023 chunks per panel-subtile
            int r = f >> 3, cc = f & 7;
            uint32_t doff = (uint32_t)(sub * 16384 + r * 128 + ((cc ^ (r & 7)) << 4));
            const __half* asrc = Af + (size_t)(m0 + r) * ZD + sub * 64 + cc * 8;
            const __half* bsrc = Bf + (size_t)(n0 + r) * ZD + sub * 64 + cc * 8;
            cp16(sbase + doff,         asrc, true);
            cp16(sbase + 49152 + doff, bsrc, true);
        }
        cp_commit();
    };
    load_sub(0);
    load_sub(1);
    load_sub(2);

    float acc[4][8][4];
    #pragma unroll
    for (int i = 0; i < 4; i++)
        #pragma unroll
        for (int j = 0; j < 8; j++)
            #pragma unroll
            for (int q = 0; q < 4; q++) acc[i][j][q] = 0.f;

    #pragma unroll
    for (int sub = 0; sub < 3; sub++) {
        if (sub == 0)      cp_wait<2>();
        else if (sub == 1) cp_wait<1>();
        else               cp_wait<0>();
        __syncthreads();

        uint32_t sA = sbase + sub * 16384;
        uint32_t sB = sbase + 49152 + sub * 16384;
        #pragma unroll
        for (int ki = 0; ki < 4; ki++) {
            uint32_t a[4][4], b[4][4];
            #pragma unroll
            for (int mt = 0; mt < 4; mt++) {
                int rr = wm * 64 + mt * 16 + ((lane >> 3) & 1) * 8 + (lane & 7);
                int kc = ki * 2 + (lane >> 4);
                uint32_t off = (uint32_t)(rr * 128 + ((kc ^ (rr & 7)) << 4));
                ldsm4(a[mt][0], a[mt][1], a[mt][2], a[mt][3], sA + off);
            }
            #pragma unroll
            for (int g = 0; g < 4; g++) {
                int rr = wn * 64 + g * 16 + (lane >> 4) * 8 + (lane & 7);
                int kc = ki * 2 + ((lane >> 3) & 1);
                uint32_t off = (uint32_t)(rr * 128 + ((kc ^ (rr & 7)) << 4));
                ldsm4(b[g][0], b[g][1], b[g][2], b[g][3], sB + off);
            }
            #pragma unroll
            for (int mt = 0; mt < 4; mt++)
                #pragma unroll
                for (int nt = 0; nt < 8; nt++)
                    mma_f16(acc[mt][nt], a[mt],
                            b[nt >> 1][(nt & 1) * 2], b[nt >> 1][(nt & 1) * 2 + 1]);
        }
    }

    #pragma unroll
    for (int mt = 0; mt < 4; mt++) {
        int row = m0 + wm * 64 + mt * 16 + (lane >> 2);
        #pragma unroll
        for (int nt = 0; nt < 8; nt++) {
            int col = n0 + wn * 64 + nt * 8 + (lane & 3) * 2;
            *(float2*)(C + (size_t)row * NN + col) =
                make_float2(acc[mt][nt][0], acc[mt][nt][1]);
            *(float2*)(C + (size_t)(row + 8) * NN + col) =
                make_float2(acc[mt][nt][2], acc[mt][nt][3]);
        }
    }
}

// ---------------- launch ----------------
static inline void* sym_addr(const void* sym) {
    void* p = nullptr;
    cudaGetSymbolAddress(&p, sym);
    return p;
}

extern "C" void kernel_launch(void* const* d_in, const int* in_sizes, int n_in,
                              void* d_out, int out_size)
{
    const float* adj = (const float*)d_in[0];
    const float* x   = (const float*)d_in[1];
    const float* W1  = (const float*)d_in[2];
    const float* W2  = (const float*)d_in[3];
    const float* Wm1 = (const float*)d_in[4];
    const float* Wm2 = (const float*)d_in[5];
    const float* Wm3 = (const float*)d_in[6];
    const float* Wt  = (const float*)d_in[7];
    const float* bt  = (const float*)d_in[8];

    float* out = (float*)d_out;
    float* out_pred = out;
    float* out_x1   = out + (size_t)NN * NN;
    float* out_x2   = out_x1 + (size_t)NN * H1;
    float* out_z    = out_x2 + (size_t)NN * H2;

    float* t1 = (float*)sym_addr(g_t1);
    float* t2 = (float*)sym_addr(g_t2);
    float* tm = (float*)sym_addr(g_tm);
    __nv_bfloat16* xh  = (__nv_bfloat16*)sym_addr(g_xh);
    __nv_bfloat16* xl  = (__nv_bfloat16*)sym_addr(g_xl);
    __nv_bfloat16* x1h = (__nv_bfloat16*)sym_addr(g_x1h);
    __nv_bfloat16* x1l = (__nv_bfloat16*)sym_addr(g_x1l);
    __nv_bfloat16* x2h = (__nv_bfloat16*)sym_addr(g_x2h);
    __nv_bfloat16* x2l = (__nv_bfloat16*)sym_addr(g_x2l);
    __nv_bfloat16* zh  = (__nv_bfloat16*)sym_addr(g_zh);
    __nv_bfloat16* zl  = (__nv_bfloat16*)sym_addr(g_zl);
    __half* zf  = (__half*)sym_addr(g_zf);
    __half* tzf = (__half*)sym_addr(g_tzf);
    __nv_bfloat16* W1h = (__nv_bfloat16*)sym_addr(g_W1h);
    __nv_bfloat16* W1l = (__nv_bfloat16*)sym_addr(g_W1l);
    __nv_bfloat16* W2h = (__nv_bfloat16*)sym_addr(g_W2h);
    __nv_bfloat16* W2l = (__nv_bfloat16*)sym_addr(g_W2l);
    __nv_bfloat16* Wmh = (__nv_bfloat16*)sym_addr(g_Wmh);
    __nv_bfloat16* Wml = (__nv_bfloat16*)sym_addr(g_Wml);
    __nv_bfloat16* Wth = (__nv_bfloat16*)sym_addr(g_Wth);
    __nv_bfloat16* Wtl = (__nv_bfloat16*)sym_addr(g_Wtl);

    cudaFuncSetAttribute((const void*)gemm3<0>,
                         cudaFuncAttributeMaxDynamicSharedMemorySize, SMEM_BYTES);
    cudaFuncSetAttribute((const void*)gemm3<1>,
                         cudaFuncAttributeMaxDynamicSharedMemorySize, SMEM_BYTES);
    cudaFuncSetAttribute((const void*)pred_f16,
                         cudaFuncAttributeMaxDynamicSharedMemorySize, PF_SMEM);

    // 0. merged split of all static inputs (single launch)
    {
        SplitArgs a;
        const float* srcs[NSEG] = {x, W1, W2, Wm1, Wm2, Wm3, Wt};
        __nv_bfloat16* his[NSEG] = {xh, W1h, W2h, Wmh, Wmh + 64 * H2, Wmh + 128 * H2, Wth};
        __nv_bfloat16* los[NSEG] = {xl, W1l, W2l, Wml, Wml + 64 * H2, Wml + 128 * H2, Wtl};
        int ns[NSEG] = {NN * IN_DIM / 4, H1 * IN_DIM / 4, H2 * H1 / 4,
                        64 * H2 / 4, 64 * H2 / 4, 64 * H2 / 4, ZD * ZD / 4};
        int off = 0;
        for (int s = 0; s < NSEG; s++) {
            a.src[s] = (const float4*)srcs[s];
            a.hi[s]  = (uint32_t*)his[s];
            a.lo[s]  = (uint32_t*)los[s];
            a.nq[s]  = ns[s];
            a.blk_off[s] = off;
            off += (ns[s] + 255) / 256;
        }
        a.blk_off[NSEG] = off;
        split_all_kernel<<<off, 256>>>(a);
    }

    build_csr_kernel<<<NN / 8, 256>>>(adj);

    // t1 = x @ W1^T
    gemm3<0><<<dim3(H1 / GBN, NN / GBM), 128, SMEM_BYTES>>>(
        xh, xl, W1h, W1l, nullptr, t1, nullptr, NN, H1, IN_DIM, H1);
    // x1 = relu(adj@t1) -> planes; out_x1 = sigmoid
    spmm4_kernel<1><<<NN / 2, 256>>>(
        (const float4*)t1, H1 / 4, 2, (float4*)out_x1,
        (uint2*)x1h, (uint2*)x1l, nullptr);
    // t2 = x1 @ W2^T
    gemm3<0><<<dim3(H2 / GBN, NN / GBM), 128, SMEM_BYTES>>>(
        x1h, x1l, W2h, W2l, nullptr, t2, nullptr, NN, H2, H1, H2);
    // x2 planes + sigmoid
    spmm4_kernel<1><<<NN / 4, 256>>>(
        (const float4*)t2, H2 / 4, 4, (float4*)out_x2,
        (uint2*)x2h, (uint2*)x2l, nullptr);
    // tm = x2 @ Wm^T
    gemm3<0><<<dim3(ZD / GBN, NN / GBM), 128, SMEM_BYTES>>>(
        x2h, x2l, Wmh, Wml, nullptr, tm, nullptr, NN, ZD, H2, ZD);
    // z = adj @ tm -> fp32 out + bf16 planes + fp16 plane
    spmm4_kernel<0><<<(NN + 4) / 5, 256>>>(
        (const float4*)tm, ZD / 4, 5, (float4*)out_z,
        (uint2*)zh, (uint2*)zl, (uint2*)zf);
    // tz = leaky(z @ Wt^T + bt) -> fp16 plane only
    gemm3<1><<<dim3(ZD / GBN, NN / GBM), 128, SMEM_BYTES>>>(
        zh, zl, Wth, Wtl, bt, nullptr, tzf, NN, ZD, ZD, ZD);
    // pred = zf @ tzf^T  (fp16 single pass, pipelined sub-tile loads)
    pred_f16<<<dim3(NN / 128, NN / 128), 128, PF_SMEM>>>(zf, tzf, out_pred);

    (void)in_sizes; (void)n_in; (void)out_size;
}

// round 17
// speedup vs baseline: 1.5377x; 1.0264x over previous
#include <cuda_runtime.h>
#include <cuda_bf16.h>
#include <cuda_fp16.h>
#include <math.h>
#include <stdint.h>

// Problem dims
#define NN      8192
#define IN_DIM  1024
#define H1      512
#define H2      256
#define ZD      192
#define CAP     192

// ---------------- device scratch ----------------
__device__ float g_t1[NN * H1];
__device__ float g_t2[NN * H2];
__device__ float g_tm[NN * ZD];
__device__ __nv_bfloat16 g_xh [NN * IN_DIM];
__device__ __nv_bfloat16 g_xl [NN * IN_DIM];
__device__ __nv_bfloat16 g_x1h[NN * H1];
__device__ __nv_bfloat16 g_x1l[NN * H1];
__device__ __nv_bfloat16 g_x2h[NN * H2];
__device__ __nv_bfloat16 g_x2l[NN * H2];
__device__ __nv_bfloat16 g_zh [NN * ZD];
__device__ __nv_bfloat16 g_zl [NN * ZD];
__device__ __half        g_zf [NN * ZD];
__device__ __half        g_tzf[NN * ZD];
__device__ __nv_bfloat16 g_W1h[H1 * IN_DIM];
__device__ __nv_bfloat16 g_W1l[H1 * IN_DIM];
__device__ __nv_bfloat16 g_W2h[H2 * H1];
__device__ __nv_bfloat16 g_W2l[H2 * H1];
__device__ __nv_bfloat16 g_Wmh[ZD * H2];
__device__ __nv_bfloat16 g_Wml[ZD * H2];
__device__ __nv_bfloat16 g_Wth[ZD * ZD];
__device__ __nv_bfloat16 g_Wtl[ZD * ZD];
__device__ float g_vals[NN * CAP];
__device__ int   g_cols[NN * CAP];
__device__ int   g_cnt [NN];

// ---------------- helpers ----------------
__device__ __forceinline__ void split2(float v0, float v1, uint32_t& hi, uint32_t& lo) {
    __nv_bfloat16 h0 = __float2bfloat16_rn(v0);
    __nv_bfloat16 h1 = __float2bfloat16_rn(v1);
    __nv_bfloat16 l0 = __float2bfloat16_rn(v0 - __bfloat162float(h0));
    __nv_bfloat16 l1 = __float2bfloat16_rn(v1 - __bfloat162float(h1));
    hi = (uint32_t)__bfloat16_as_ushort(h0) | ((uint32_t)__bfloat16_as_ushort(h1) << 16);
    lo = (uint32_t)__bfloat16_as_ushort(l0) | ((uint32_t)__bfloat16_as_ushort(l1) << 16);
}

__device__ __forceinline__ uint32_t h2_as_u32(__half2 h) {
    uint32_t u;
    memcpy(&u, &h, 4);
    return u;
}

__device__ __forceinline__ void ldsm4(uint32_t& r0, uint32_t& r1, uint32_t& r2,
                                      uint32_t& r3, uint32_t addr) {
    asm volatile("ldmatrix.sync.aligned.m8n8.x4.shared.b16 {%0,%1,%2,%3}, [%4];"
                 : "=r"(r0), "=r"(r1), "=r"(r2), "=r"(r3) : "r"(addr));
}

__device__ __forceinline__ void mma_bf16(float (&d)[4], const uint32_t (&a)[4],
                                         uint32_t b0, uint32_t b1) {
    asm volatile(
        "mma.sync.aligned.m16n8k16.row.col.f32.bf16.bf16.f32 "
        "{%0,%1,%2,%3}, {%4,%5,%6,%7}, {%8,%9}, {%0,%1,%2,%3};"
        : "+f"(d[0]), "+f"(d[1]), "+f"(d[2]), "+f"(d[3])
        : "r"(a[0]), "r"(a[1]), "r"(a[2]), "r"(a[3]), "r"(b0), "r"(b1));
}

__device__ __forceinline__ void mma_f16(float (&d)[4], const uint32_t (&a)[4],
                                        uint32_t b0, uint32_t b1) {
    asm volatile(
        "mma.sync.aligned.m16n8k16.row.col.f32.f16.f16.f32 "
        "{%0,%1,%2,%3}, {%4,%5,%6,%7}, {%8,%9}, {%0,%1,%2,%3};"
        : "+f"(d[0]), "+f"(d[1]), "+f"(d[2]), "+f"(d[3])
        : "r"(a[0]), "r"(a[1]), "r"(a[2]), "r"(a[3]), "r"(b0), "r"(b1));
}

__device__ __forceinline__ void cp16(uint32_t dst, const void* src, bool v) {
    int sz = v ? 16 : 0;
    asm volatile("cp.async.cg.shared.global [%0], [%1], 16, %2;\n"
                 :: "r"(dst), "l"(src), "r"(sz) : "memory");
}
__device__ __forceinline__ void cp_commit() {
    asm volatile("cp.async.commit_group;" ::: "memory");
}
template <int n>
__device__ __forceinline__ void cp_wait() {
    asm volatile("cp.async.wait_group %0;" :: "n"(n) : "memory");
}

// ---------------- fused prologue: CSR build + split, one launch ----------------
// Blocks [0, CSR_BLOCKS): adjacency scan (8 rows per 256-thread block).
// Blocks [CSR_BLOCKS, ...): fp32 -> bf16 hi/lo split segments.
// Neither path uses smem -> no occupancy poisoning; CSR first = long pole
// starts immediately, split backfills; independent inputs/outputs.
#define NSEG 7
#define CSR_BLOCKS (NN / 8)
struct ProArgs {
    const float*  adj;
    const float4* src[NSEG];
    uint32_t*     hi [NSEG];
    uint32_t*     lo [NSEG];
    int blk_off[NSEG + 1];   // split-block offsets (relative)
    int nq[NSEG];
};

__device__ __forceinline__ void csr_row_body(const float* __restrict__ adj, int row) {
    int lane = threadIdx.x & 31;
    const float* arow = adj + (size_t)row * NN;
    int cnt = 0;
    for (int c0 = 0; c0 < NN; c0 += 128) {
        float4 v = *(const float4*)(arow + c0 + lane * 4);
        unsigned m = (v.x != 0.f ? 1u : 0u) | (v.y != 0.f ? 2u : 0u)
                   | (v.z != 0.f ? 4u : 0u) | (v.w != 0.f ? 8u : 0u);
        int c = __popc(m);
        int s = c;
        #pragma unroll
        for (int d = 1; d < 32; d <<= 1) {
            int t = __shfl_up_sync(0xffffffffu, s, d);
            if (lane >= d) s += t;
        }
        int pos = cnt + s - c;
        int base = c0 + lane * 4;
        float vv[4] = {v.x, v.y, v.z, v.w};
        #pragma unroll
        for (int e = 0; e < 4; e++) {
            if ((m >> e) & 1u) {
                if (pos < CAP) {
                    g_cols[row * CAP + pos] = base + e;
                    g_vals[row * CAP + pos] = vv[e];
                }
                pos++;
            }
        }
        cnt += __shfl_sync(0xffffffffu, s, 31);
    }
    if (lane == 0) g_cnt[row] = (cnt < CAP) ? cnt : CAP;
}

__global__ void __launch_bounds__(256) prologue_kernel(ProArgs a) {
    int b = blockIdx.x;
    if (b < CSR_BLOCKS) {
        int row = b * 8 + (threadIdx.x >> 5);
        if (row < NN) csr_row_body(a.adj, row);
        return;
    }
    b -= CSR_BLOCKS;
    int s = 0;
    #pragma unroll
    for (int k = 1; k < NSEG; k++)
        if (b >= a.blk_off[k]) s = k;
    int i = (b - a.blk_off[s]) * 256 + threadIdx.x;
    if (i >= a.nq[s]) return;
    float4 v = a.src[s][i];
    uint32_t h0, l0, h1, l1;
    split2(v.x, v.y, h0, l0);
    split2(v.z, v.w, h1, l1);
    a.hi[s][i * 2]     = h0; a.hi[s][i * 2 + 1] = h1;
    a.lo[s][i * 2]     = l0; a.lo[s][i * 2 + 1] = l1;
}

// ---------------- SpMM, float4-vectorized, unroll-8 gathers (at LTS cap) ----
template <int MODE>
__global__ void __launch_bounds__(256) spmm4_kernel(
    const float4* __restrict__ X, int ncq, int rpc,
    float4* __restrict__ out_f32,
    uint2* __restrict__ hi, uint2* __restrict__ lo,
    uint2* __restrict__ f16out)
{
    int t = threadIdx.x;
    int r = t / ncq;
    int c = t - r * ncq;
    int row = blockIdx.x * rpc + r;
    if (r >= rpc || row >= NN) return;

    int cnt = g_cnt[row];
    const int*   cols = g_cols + row * CAP;
    const float* vals = g_vals + row * CAP;

    float4 a0 = {0,0,0,0}, a1 = {0,0,0,0}, a2 = {0,0,0,0}, a3 = {0,0,0,0};
    int j = 0;
    for (; j + 8 <= cnt; j += 8) {
        int   c0 = cols[j+0], c1 = cols[j+1], c2 = cols[j+2], c3 = cols[j+3];
        int   c4 = cols[j+4], c5 = cols[j+5], c6 = cols[j+6], c7 = cols[j+7];
        float v0 = vals[j+0], v1 = vals[j+1], v2 = vals[j+2], v3 = vals[j+3];
        float v4 = vals[j+4], v5 = vals[j+5], v6 = vals[j+6], v7 = vals[j+7];
        float4 x0 = X[(size_t)c0 * ncq + c];
        float4 x1 = X[(size_t)c1 * ncq + c];
        float4 x2 = X[(size_t)c2 * ncq + c];
        float4 x3 = X[(size_t)c3 * ncq + c];
        float4 x4 = X[(size_t)c4 * ncq + c];
        float4 x5 = X[(size_t)c5 * ncq + c];
        float4 x6 = X[(size_t)c6 * ncq + c];
        float4 x7 = X[(size_t)c7 * ncq + c];
        a0.x += v0 * x0.x; a0.y += v0 * x0.y; a0.z += v0 * x0.z; a0.w += v0 * x0.w;
        a1.x += v1 * x1.x; a1.y += v1 * x1.y; a1.z += v1 * x1.z; a1.w += v1 * x1.w;
        a2.x += v2 * x2.x; a2.y += v2 * x2.y; a2.z += v2 * x2.z; a2.w += v2 * x2.w;
        a3.x += v3 * x3.x; a3.y += v3 * x3.y; a3.z += v3 * x3.z; a3.w += v3 * x3.w;
        a0.x += v4 * x4.x; a0.y += v4 * x4.y; a0.z += v4 * x4.z; a0.w += v4 * x4.w;
        a1.x += v5 * x5.x; a1.y += v5 * x5.y; a1.z += v5 * x5.z; a1.w += v5 * x5.w;
        a2.x += v6 * x6.x; a2.y += v6 * x6.y; a2.z += v6 * x6.z; a2.w += v6 * x6.w;
        a3.x += v7 * x7.x; a3.y += v7 * x7.y; a3.z += v7 * x7.z; a3.w += v7 * x7.w;
    }
    if (j + 4 <= cnt) {
        int   c0 = cols[j+0], c1 = cols[j+1], c2 = cols[j+2], c3 = cols[j+3];
        float v0 = vals[j+0], v1 = vals[j+1], v2 = vals[j+2], v3 = vals[j+3];
        float4 x0 = X[(size_t)c0 * ncq + c];
        float4 x1 = X[(size_t)c1 * ncq + c];
        float4 x2 = X[(size_t)c2 * ncq + c];
        float4 x3 = X[(size_t)c3 * ncq + c];
        a0.x += v0 * x0.x; a0.y += v0 * x0.y; a0.z += v0 * x0.z; a0.w += v0 * x0.w;
        a1.x += v1 * x1.x; a1.y += v1 * x1.y; a1.z += v1 * x1.z; a1.w += v1 * x1.w;
        a2.x += v2 * x2.x; a2.y += v2 * x2.y; a2.z += v2 * x2.z; a2.w += v2 * x2.w;
        a3.x += v3 * x3.x; a3.y += v3 * x3.y; a3.z += v3 * x3.z; a3.w += v3 * x3.w;
        j += 4;
    }
    for (; j < cnt; j++) {
        float v = vals[j];
        float4 xv = X[(size_t)cols[j] * ncq + c];
        a0.x += v * xv.x; a0.y += v * xv.y; a0.z += v * xv.z; a0.w += v * xv.w;
    }
    float4 acc;
    acc.x = (a0.x + a1.x) + (a2.x + a3.x);
    acc.y = (a0.y + a1.y) + (a2.y + a3.y);
    acc.z = (a0.z + a1.z) + (a2.z + a3.z);
    acc.w = (a0.w + a1.w) + (a2.w + a3.w);

    size_t o = (size_t)row * ncq + c;
    float4 rr;
    if (MODE == 1) {
        rr.x = acc.x > 0.f ? acc.x : 0.f;
        rr.y = acc.y > 0.f ? acc.y : 0.f;
        rr.z = acc.z > 0.f ? acc.z : 0.f;
        rr.w = acc.w > 0.f ? acc.w : 0.f;
    } else {
        rr = acc;
    }
    uint2 h, l;
    split2(rr.x, rr.y, h.x, l.x);
    split2(rr.z, rr.w, h.y, l.y);
    hi[o] = h;
    lo[o] = l;
    if (MODE == 0) {
        uint2 f;
        f.x = h2_as_u32(__floats2half2_rn(rr.x, rr.y));
        f.y = h2_as_u32(__floats2half2_rn(rr.z, rr.w));
        f16out[o] = f;
        out_f32[o] = acc;
    } else {
        float4 s;
        s.x = 1.0f / (1.0f + __expf(-rr.x));
        s.y = 1.0f / (1.0f + __expf(-rr.y));
        s.z = 1.0f / (1.0f + __expf(-rr.z));
        s.w = 1.0f / (1.0f + __expf(-rr.w));
        out_f32[o] = s;
    }
}

// ---------------- bf16x3 mma.sync GEMM, 128x64 tiles, 4 CTAs/SM ----------------
#define GBM 128
#define GBN 64
#define GBK 32
#define STG_BYTES 24576
#define NSTAGE 2
#define SMEM_BYTES (NSTAGE * STG_BYTES)
#define PL_AH 0
#define PL_AL 8192
#define PL_BH 16384
#define PL_BL 20480

__device__ __forceinline__ uint32_t sw_off(int r, int kc) {
    return (uint32_t)(r * 64 + ((kc ^ ((r >> 1) & 3)) << 4));
}

// EPI 0: fp32 store. EPI 1: +bias, leaky_relu(0.1) -> fp16 plane only.
template <int EPI>
__global__ void __launch_bounds__(128, 4) gemm3(
    const __nv_bfloat16* __restrict__ Ah, const __nv_bfloat16* __restrict__ Al,
    const __nv_bfloat16* __restrict__ Bh, const __nv_bfloat16* __restrict__ Bl,
    const float* __restrict__ bias, float* __restrict__ C,
    __half* __restrict__ Cf,
    int M, int N, int K, int ldc)
{
    extern __shared__ uint8_t smem[];
    const uint32_t sbase = (uint32_t)__cvta_generic_to_shared(smem);

    const int tid  = threadIdx.x;
    const int lane = tid & 31;
    const int wid  = tid >> 5;
    const int wm   = wid & 1;
    const int wn   = wid >> 1;
    const int m0   = blockIdx.y * GBM;
    const int n0   = blockIdx.x * GBN;

    float acc[4][4][4];
    #pragma unroll
    for (int i = 0; i < 4; i++)
        #pragma unroll
        for (int j = 0; j < 4; j++)
            #pragma unroll
            for (int q = 0; q < 4; q++) acc[i][j][q] = 0.f;

    auto load_tile = [&](int it, int s) {
        int k0 = it * GBK;
        uint32_t st = sbase + s * STG_BYTES;
        #pragma unroll
        for (int i = 0; i < 4; i++) {
            int f = tid + i * 128;
            int r = f >> 2, c = f & 3;
            uint32_t doff = sw_off(r, c);
            size_t aoff = (size_t)(m0 + r) * K + k0 + c * 8;
            cp16(st + PL_AH + doff, Ah + aoff, true);
            cp16(st + PL_AL + doff, Al + aoff, true);
        }
        #pragma unroll
        for (int i = 0; i < 2; i++) {
            int f = tid + i * 128;
            int r = f >> 2, c = f & 3;
            uint32_t doff = sw_off(r, c);
            bool bv = (n0 + r) < N;
            int  br = bv ? (n0 + r) : 0;
            size_t boff = (size_t)br * K + k0 + c * 8;
            cp16(st + PL_BH + doff, Bh + boff, bv);
            cp16(st + PL_BL + doff, Bl + boff, bv);
        }
        cp_commit();
    };

    const int nIt = K / GBK;
    load_tile(0, 0);

    for (int it = 0; it < nIt; it++) {
        if (it + 1 < nIt) {
            load_tile(it + 1, (it + 1) & 1);
            cp_wait<1>();
        } else {
            cp_wait<0>();
        }
        __syncthreads();

        uint32_t st = sbase + (it & 1) * STG_BYTES;
        #pragma unroll
        for (int ks = 0; ks < 2; ks++) {
            uint32_t bh[2][4], bl[2][4];
            #pragma unroll
            for (int g = 0; g < 2; g++) {
                int rr = wn * 32 + g * 16 + (lane >> 4) * 8 + (lane & 7);
                int kc = ks * 2 + ((lane >> 3) & 1);
                uint32_t off = sw_off(rr, kc);
                ldsm4(bh[g][0], bh[g][1], bh[g][2], bh[g][3], st + PL_BH + off);
                ldsm4(bl[g][0], bl[g][1], bl[g][2], bl[g][3], st + PL_BL + off);
            }
            #pragma unroll
            for (int mt = 0; mt < 4; mt++) {
                uint32_t ah[4], al[4];
                int rr = wm * 64 + mt * 16 + ((lane >> 3) & 1) * 8 + (lane & 7);
                int kc = ks * 2 + (lane >> 4);
                uint32_t off = sw_off(rr, kc);
                ldsm4(ah[0], ah[1], ah[2], ah[3], st + PL_AH + off);
                ldsm4(al[0], al[1], al[2], al[3], st + PL_AL + off);
                #pragma unroll
                for (int nt = 0; nt < 4; nt++) {
                    uint32_t b0 = bh[nt >> 1][(nt & 1) * 2];
                    uint32_t b1 = bh[nt >> 1][(nt & 1) * 2 + 1];
                    mma_bf16(acc[mt][nt], ah, b0, b1);
                    mma_bf16(acc[mt][nt], al, b0, b1);
                    mma_bf16(acc[mt][nt], ah,
                             bl[nt >> 1][(nt & 1) * 2], bl[nt >> 1][(nt & 1) * 2 + 1]);
                }
            }
        }
        __syncthreads();
    }

    #pragma unroll
    for (int mt = 0; mt < 4; mt++) {
        int row = m0 + wm * 64 + mt * 16 + (lane >> 2);
        #pragma unroll
        for (int nt = 0; nt < 4; nt++) {
            int col = n0 + wn * 32 + nt * 8 + (lane & 3) * 2;
            if (col < N) {
                float c0 = acc[mt][nt][0], c1 = acc[mt][nt][1];
                float c2 = acc[mt][nt][2], c3 = acc[mt][nt][3];
                if (EPI == 1) {
                    float b0 = bias[col], b1 = bias[col + 1];
                    c0 += b0; c1 += b1; c2 += b0; c3 += b1;
                    c0 = (c0 >= 0.f) ? c0 : 0.1f * c0;
                    c1 = (c1 >= 0.f) ? c1 : 0.1f * c1;
                    c2 = (c2 >= 0.f) ? c2 : 0.1f * c2;
                    c3 = (c3 >= 0.f) ? c3 : 0.1f * c3;
                    *(__half2*)(Cf + (size_t)row * ldc + col)       = __floats2half2_rn(c0, c1);
                    *(__half2*)(Cf + (size_t)(row + 8) * ldc + col) = __floats2half2_rn(c2, c3);
                } else {
                    *(float2*)(C + (size_t)row * ldc + col)       = make_float2(c0, c1);
                    *(float2*)(C + (size_t)(row + 8) * ldc + col) = make_float2(c2, c3);
                }
            }
        }
    }
}

// ---------------- fp16 single-pass pred kernel, sub-tile pipelined loads -------
#define PF_SMEM 98304

__global__ void __launch_bounds__(128, 2) pred_f16(
    const __half* __restrict__ Af, const __half* __restrict__ Bf,
    float* __restrict__ C)
{
    extern __shared__ uint8_t smem[];
    const uint32_t sbase = (uint32_t)__cvta_generic_to_shared(smem);
    const int tid  = threadIdx.x;
    const int lane = tid & 31;
    const int wid  = tid >> 5;
    const int wm   = wid & 1;
    const int wn   = wid >> 1;
    const int m0   = blockIdx.y * 128;
    const int n0   = blockIdx.x * 128;

    auto load_sub = [&](int sub) {
        #pragma unroll
        for (int i = 0; i < 8; i++) {
            int f = tid + i * 128;
            int r = f >> 3, cc = f & 7;
            uint32_t doff = (uint32_t)(sub * 16384 + r * 128 + ((cc ^ (r & 7)) << 4));
            const __half* asrc = Af + (size_t)(m0 + r) * ZD + sub * 64 + cc * 8;
            const __half* bsrc = Bf + (size_t)(n0 + r) * ZD + sub * 64 + cc * 8;
            cp16(sbase + doff,         asrc, true);
            cp16(sbase + 49152 + doff, bsrc, true);
        }
        cp_commit();
    };
    load_sub(0);
    load_sub(1);
    load_sub(2);

    float acc[4][8][4];
    #pragma unroll
    for (int i = 0; i < 4; i++)
        #pragma unroll
        for (int j = 0; j < 8; j++)
            #pragma unroll
            for (int q = 0; q < 4; q++) acc[i][j][q] = 0.f;

    #pragma unroll
    for (int sub = 0; sub < 3; sub++) {
        if (sub == 0)      cp_wait<2>();
        else if (sub == 1) cp_wait<1>();
        else               cp_wait<0>();
        __syncthreads();

        uint32_t sA = sbase + sub * 16384;
        uint32_t sB = sbase + 49152 + sub * 16384;
        #pragma unroll
        for (int ki = 0; ki < 4; ki++) {
            uint32_t a[4][4], b[4][4];
            #pragma unroll
            for (int mt = 0; mt < 4; mt++) {
                int rr = wm * 64 + mt * 16 + ((lane >> 3) & 1) * 8 + (lane & 7);
                int kc = ki * 2 + (lane >> 4);
                uint32_t off = (uint32_t)(rr * 128 + ((kc ^ (rr & 7)) << 4));
                ldsm4(a[mt][0], a[mt][1], a[mt][2], a[mt][3], sA + off);
            }
            #pragma unroll
            for (int g = 0; g < 4; g++) {
                int rr = wn * 64 + g * 16 + (lane >> 4) * 8 + (lane & 7);
                int kc = ki * 2 + ((lane >> 3) & 1);
                uint32_t off = (uint32_t)(rr * 128 + ((kc ^ (rr & 7)) << 4));
                ldsm4(b[g][0], b[g][1], b[g][2], b[g][3], sB + off);
            }
            #pragma unroll
            for (int mt = 0; mt < 4; mt++)
                #pragma unroll
                for (int nt = 0; nt < 8; nt++)
                    mma_f16(acc[mt][nt], a[mt],
                            b[nt >> 1][(nt & 1) * 2], b[nt >> 1][(nt & 1) * 2 + 1]);
        }
    }

    #pragma unroll
    for (int mt = 0; mt < 4; mt++) {
        int row = m0 + wm * 64 + mt * 16 + (lane >> 2);
        #pragma unroll
        for (int nt = 0; nt < 8; nt++) {
            int col = n0 + wn * 64 + nt * 8 + (lane & 3) * 2;
            *(float2*)(C + (size_t)row * NN + col) =
                make_float2(acc[mt][nt][0], acc[mt][nt][1]);
            *(float2*)(C + (size_t)(row + 8) * NN + col) =
                make_float2(acc[mt][nt][2], acc[mt][nt][3]);
        }
    }
}

// ---------------- launch ----------------
static inline void* sym_addr(const void* sym) {
    void* p = nullptr;
    cudaGetSymbolAddress(&p, sym);
    return p;
}

extern "C" void kernel_launch(void* const* d_in, const int* in_sizes, int n_in,
                              void* d_out, int out_size)
{
    const float* adj = (const float*)d_in[0];
    const float* x   = (const float*)d_in[1];
    const float* W1  = (const float*)d_in[2];
    const float* W2  = (const float*)d_in[3];
    const float* Wm1 = (const float*)d_in[4];
    const float* Wm2 = (const float*)d_in[5];
    const float* Wm3 = (const float*)d_in[6];
    const float* Wt  = (const float*)d_in[7];
    const float* bt  = (const float*)d_in[8];

    float* out = (float*)d_out;
    float* out_pred = out;
    float* out_x1   = out + (size_t)NN * NN;
    float* out_x2   = out_x1 + (size_t)NN * H1;
    float* out_z    = out_x2 + (size_t)NN * H2;

    float* t1 = (float*)sym_addr(g_t1);
    float* t2 = (float*)sym_addr(g_t2);
    float* tm = (float*)sym_addr(g_tm);
    __nv_bfloat16* xh  = (__nv_bfloat16*)sym_addr(g_xh);
    __nv_bfloat16* xl  = (__nv_bfloat16*)sym_addr(g_xl);
    __nv_bfloat16* x1h = (__nv_bfloat16*)sym_addr(g_x1h);
    __nv_bfloat16* x1l = (__nv_bfloat16*)sym_addr(g_x1l);
    __nv_bfloat16* x2h = (__nv_bfloat16*)sym_addr(g_x2h);
    __nv_bfloat16* x2l = (__nv_bfloat16*)sym_addr(g_x2l);
    __nv_bfloat16* zh  = (__nv_bfloat16*)sym_addr(g_zh);
    __nv_bfloat16* zl  = (__nv_bfloat16*)sym_addr(g_zl);
    __half* zf  = (__half*)sym_addr(g_zf);
    __half* tzf = (__half*)sym_addr(g_tzf);
    __nv_bfloat16* W1h = (__nv_bfloat16*)sym_addr(g_W1h);
    __nv_bfloat16* W1l = (__nv_bfloat16*)sym_addr(g_W1l);
    __nv_bfloat16* W2h = (__nv_bfloat16*)sym_addr(g_W2h);
    __nv_bfloat16* W2l = (__nv_bfloat16*)sym_addr(g_W2l);
    __nv_bfloat16* Wmh = (__nv_bfloat16*)sym_addr(g_Wmh);
    __nv_bfloat16* Wml = (__nv_bfloat16*)sym_addr(g_Wml);
    __nv_bfloat16* Wth = (__nv_bfloat16*)sym_addr(g_Wth);
    __nv_bfloat16* Wtl = (__nv_bfloat16*)sym_addr(g_Wtl);

    cudaFuncSetAttribute((const void*)gemm3<0>,
                         cudaFuncAttributeMaxDynamicSharedMemorySize, SMEM_BYTES);
    cudaFuncSetAttribute((const void*)gemm3<1>,
                         cudaFuncAttributeMaxDynamicSharedMemorySize, SMEM_BYTES);
    cudaFuncSetAttribute((const void*)pred_f16,
                         cudaFuncAttributeMaxDynamicSharedMemorySize, PF_SMEM);

    // 0. fused prologue: CSR scan (blocks first) + bf16 splits, one launch
    {
        ProArgs a;
        a.adj = adj;
        const float* srcs[NSEG] = {x, W1, W2, Wm1, Wm2, Wm3, Wt};
        __nv_bfloat16* his[NSEG] = {xh, W1h, W2h, Wmh, Wmh + 64 * H2, Wmh + 128 * H2, Wth};
        __nv_bfloat16* los[NSEG] = {xl, W1l, W2l, Wml, Wml + 64 * H2, Wml + 128 * H2, Wtl};
        int ns[NSEG] = {NN * IN_DIM / 4, H1 * IN_DIM / 4, H2 * H1 / 4,
                        64 * H2 / 4, 64 * H2 / 4, 64 * H2 / 4, ZD * ZD / 4};
        int off = 0;
        for (int s = 0; s < NSEG; s++) {
            a.src[s] = (const float4*)srcs[s];
            a.hi[s]  = (uint32_t*)his[s];
            a.lo[s]  = (uint32_t*)los[s];
            a.nq[s]  = ns[s];
            a.blk_off[s] = off;
            off += (ns[s] + 255) / 256;
        }
        a.blk_off[NSEG] = off;
        prologue_kernel<<<CSR_BLOCKS + off, 256>>>(a);
    }

    // t1 = x @ W1^T
    gemm3<0><<<dim3(H1 / GBN, NN / GBM), 128, SMEM_BYTES>>>(
        xh, xl, W1h, W1l, nullptr, t1, nullptr, NN, H1, IN_DIM, H1);
    // x1 = relu(adj@t1) -> planes; out_x1 = sigmoid
    spmm4_kernel<1><<<NN / 2, 256>>>(
        (const float4*)t1, H1 / 4, 2, (float4*)out_x1,
        (uint2*)x1h, (uint2*)x1l, nullptr);
    // t2 = x1 @ W2^T
    gemm3<0><<<dim3(H2 / GBN, NN / GBM), 128, SMEM_BYTES>>>(
        x1h, x1l, W2h, W2l, nullptr, t2, nullptr, NN, H2, H1, H2);
    // x2 planes + sigmoid
    spmm4_kernel<1><<<NN / 4, 256>>>(
        (const float4*)t2, H2 / 4, 4, (float4*)out_x2,
        (uint2*)x2h, (uint2*)x2l, nullptr);
    // tm = x2 @ Wm^T
    gemm3<0><<<dim3(ZD / GBN, NN / GBM), 128, SMEM_BYTES>>>(
        x2h, x2l, Wmh, Wml, nullptr, tm, nullptr, NN, ZD, H2, ZD);
    // z = adj @ tm -> fp32 out + bf16 planes + fp16 plane
    spmm4_kernel<0><<<(NN + 4) / 5, 256>>>(
        (const float4*)tm, ZD / 4, 5, (float4*)out_z,
        (uint2*)zh, (uint2*)zl, (uint2*)zf);
    // tz = leaky(z @ Wt^T + bt) -> fp16 plane only
    gemm3<1><<<dim3(ZD / GBN, NN / GBM), 128, SMEM_BYTES>>>(
        zh, zl, Wth, Wtl, bt, nullptr, tzf, NN, ZD, ZD, ZD);
    // pred = zf @ tzf^T  (fp16 single pass, pipelined sub-tile loads)
    pred_f16<<<dim3(NN / 128, NN / 128), 128, PF_SMEM>>>(zf, tzf, out_pred);

    (void)in_sizes; (void)n_in; (void)out_size;
}